// round 12
// baseline (speedup 1.0000x reference)
#include <cuda_runtime.h>
#include <cuda_bf16.h>
#include <math.h>

#define BB 32
#define TT 512
#define DIN 1824
#define HH 512
#define G4 2048
#define KK 30
#define TSTART 28
#define TSTOP 29
#define NEGV (-10000.0f)
#define MTOT (TT*BB)            /* 16384 */

// ------------------------- device scratch -------------------------
__device__ __nv_bfloat16 g_xwb[2][(size_t)MTOT*G4];  // input proj, bf16
__device__ __nv_bfloat16 g_hsb[(size_t)MTOT*2*HH];   // [m][hf|hb] bf16, m=t*B+b
__device__ float g_feats[(size_t)BB*TT*KK];          // [b][t][k]
__device__ __nv_bfloat16 g_xb[(size_t)MTOT*DIN];     // gathered embeddings, bf16
__device__ __nv_bfloat16 g_wb[2][(size_t)DIN*G4];    // W_ih f/b, bf16
__device__ __nv_bfloat16 g_wb2[2][(size_t)HH*G4];    // W_hh f/b, bf16
__device__ unsigned g_tile_ctr;                      // GEMM tile work counter
__device__ unsigned g_grpcnt[2][128];                // per (dir, t-group of 4) done count

__device__ __forceinline__ unsigned smaddr(const void* p)
{
    return (unsigned)__cvta_generic_to_shared(p);
}

__device__ __forceinline__ float tanha(float x)
{
    float r;
    asm("tanh.approx.f32 %0, %1;" : "=f"(r) : "f"(x));
    return r;
}

// ------------------------- cast kernels -------------------------
__global__ __launch_bounds__(256) void k_castx(const float* __restrict__ embed,
                                               const int* __restrict__ ids)
{
    size_t idx = (size_t)blockIdx.x * 256 + threadIdx.x;
    if (idx >= (size_t)MTOT * (DIN / 4)) return;
    int m = (int)(idx / (DIN / 4));
    int q = (int)(idx % (DIN / 4));
    int id = ids[(m & 31) * TT + (m >> 5)];
    float4 v = *(const float4*)(embed + (size_t)id * DIN + 4 * q);
    __nv_bfloat162 lo = __floats2bfloat162_rn(v.x, v.y);
    __nv_bfloat162 hi = __floats2bfloat162_rn(v.z, v.w);
    uint2 pk; pk.x = *(unsigned*)&lo; pk.y = *(unsigned*)&hi;
    *(uint2*)(g_xb + (size_t)m * DIN + 4 * q) = pk;
}

#define NW4 ((size_t)DIN*G4/4)
#define NH4 ((size_t)HH*G4/4)

__global__ __launch_bounds__(256) void k_castw(const float* __restrict__ f0,
                                               const float* __restrict__ f1,
                                               const float* __restrict__ f2,
                                               const float* __restrict__ f3)
{
    if (blockIdx.x == 0) {
        if (threadIdx.x == 0) g_tile_ctr = 0;
        if (threadIdx.x < 256) ((unsigned*)g_grpcnt)[threadIdx.x] = 0;
    }
    size_t idx = (size_t)blockIdx.x * 256 + threadIdx.x;
    const float* src; __nv_bfloat16* dst;
    if (idx < NW4)                    { src = f0; dst = g_wb[0]; }
    else if (idx < 2 * NW4)           { src = f1; dst = g_wb[1]; idx -= NW4; }
    else if (idx < 2 * NW4 + NH4)     { src = f2; dst = g_wb2[0]; idx -= 2 * NW4; }
    else if (idx < 2 * NW4 + 2 * NH4) { src = f3; dst = g_wb2[1]; idx -= 2 * NW4 + NH4; }
    else return;
    float4 v = *(const float4*)(src + 4 * idx);
    __nv_bfloat162 lo = __floats2bfloat162_rn(v.x, v.y);
    __nv_bfloat162 hi = __floats2bfloat162_rn(v.z, v.w);
    uint2 pk; pk.x = *(unsigned*)&lo; pk.y = *(unsigned*)&hi;
    *(uint2*)(dst + 4 * idx) = pk;
}

// ------------------------- fused kernel geometry -------------------------
#define BM 128
#define BN 128
#define BK 32
#define NKT (DIN / BK)   /* 57 */
#define GA_STRIDE (BK + 8)
#define GB_STRIDE (BN + 8)
#define GA_BUF (BM * GA_STRIDE)
#define GB_BUF (BK * GB_STRIDE)

#define WPAD 136
#define SPAD 520
#define GPAD 136
#define STG_ROW   (SPAD*2)              /* 1040 B */
#define STG_PAR   (16*STG_ROW)          /* 16640 B */
#define OFF_STG   (512*WPAD*2)          /* 139264 */
#define OFF_GATES (OFF_STG + 2*STG_PAR) /* 172544 */
#define OFF_MBAR  (OFF_GATES + 2*16*GPAD*4)
#define LSM_BYTES (OFF_MBAR + 64)

// GEMM tiles: 128 t-groups x (2 dirs x 16 n-tiles) = 4096. Order: both ends inward.
#define NTILES 4096u

// ------------------------- fused: 4 LSTM clusters + 4 GEMM worker clusters -----------
// grid = 128 CTAs = 8 clusters of 16 -> 4 clusters per die, ALL co-resident in wave 1.
__global__ __launch_bounds__(512, 1) __cluster_dims__(16, 1, 1)
void k_fused(const float* __restrict__ bf_, const float* __restrict__ bb_)
{
    extern __shared__ char smraw[];
    int tid = threadIdx.x;
    int wid = tid >> 5;
    int lane = tid & 31;
    int cid = blockIdx.x >> 4;

    if (cid >= 4) {
        // ===================== GEMM worker (64 CTAs) =====================
        __nv_bfloat16* As = (__nv_bfloat16*)smraw;          // [3][128][40]
        __nv_bfloat16* Bs = As + 3 * GA_BUF;                // [3][32][136]
        unsigned* tslot = (unsigned*)(smraw + OFF_MBAR + 16);
        int wr = wid & 3;           // m warp group (m32)
        int wc = wid >> 2;          // n warp group (n32)

        for (;;) {
            if (tid == 0) *tslot = atomicAdd(&g_tile_ctr, 1u);
            __syncthreads();
            unsigned ti = *tslot;
            if (ti >= NTILES) return;
            __syncthreads();
            int gg = (int)(ti >> 5), qq = (int)(ti & 31);
            int dirw = qq >> 4, nt = qq & 15;
            int tg = dirw ? (127 - gg) : gg;
            int m0 = tg * 128, n0 = nt * 128;
            const float* bias = dirw ? bb_ : bf_;
            const __nv_bfloat16* A = g_xb;
            const __nv_bfloat16* Bw = g_wb[dirw];
            __nv_bfloat16* outp = g_xwb[dirw];

            float acc[2][4][4];
#pragma unroll
            for (int i = 0; i < 2; i++)
#pragma unroll
                for (int j = 0; j < 4; j++)
#pragma unroll
                    for (int r = 0; r < 4; r++) acc[i][j][r] = 0.f;

            auto loadAB = [&](int buf, int k0) {
                __nv_bfloat16* Ab = As + buf * GA_BUF;
                __nv_bfloat16* Bb = Bs + buf * GB_BUF;
                {
                    int r = tid >> 2, q4 = tid & 3;
                    unsigned dst = smaddr(Ab + r * GA_STRIDE + q4 * 8);
                    const __nv_bfloat16* src = A + (size_t)(m0 + r) * DIN + k0 + q4 * 8;
                    asm volatile("cp.async.cg.shared.global [%0], [%1], 16;\n" :: "r"(dst), "l"(src));
                }
                {
                    int r = tid >> 4, q16 = tid & 15;
                    unsigned dst = smaddr(Bb + r * GB_STRIDE + q16 * 8);
                    const __nv_bfloat16* src = Bw + (size_t)(k0 + r) * G4 + n0 + q16 * 8;
                    asm volatile("cp.async.cg.shared.global [%0], [%1], 16;\n" :: "r"(dst), "l"(src));
                }
            };

            loadAB(0, 0);
            asm volatile("cp.async.commit_group;\n");
            loadAB(1, BK);
            asm volatile("cp.async.commit_group;\n");

            int buf = 0;
            for (int kt = 0; kt < NKT; kt++) {
                asm volatile("cp.async.wait_group 1;\n");
                __syncthreads();
                if (kt + 2 < NKT) {
                    int nb = buf + 2; if (nb >= 3) nb -= 3;
                    loadAB(nb, (kt + 2) * BK);
                }
                asm volatile("cp.async.commit_group;\n");

                __nv_bfloat16* Ab = As + buf * GA_BUF;
                __nv_bfloat16* Bb = Bs + buf * GB_BUF;
#pragma unroll
                for (int ks = 0; ks < 2; ks++) {
                    int k0 = ks * 16;
                    unsigned a[2][4];
#pragma unroll
                    for (int mi = 0; mi < 2; mi++) {
                        unsigned addr = smaddr(Ab + (wr * 32 + mi * 16 + (lane & 15)) * GA_STRIDE + k0 + 8 * (lane >> 4));
                        asm volatile("ldmatrix.sync.aligned.m8n8.x4.shared.b16 {%0,%1,%2,%3}, [%4];\n"
                                     : "=r"(a[mi][0]), "=r"(a[mi][1]), "=r"(a[mi][2]), "=r"(a[mi][3])
                                     : "r"(addr));
                    }
                    unsigned b[2][4];
#pragma unroll
                    for (int nj = 0; nj < 2; nj++) {
                        unsigned addr = smaddr(Bb + (k0 + (lane & 15)) * GB_STRIDE + wc * 32 + nj * 16 + 8 * (lane >> 4));
                        asm volatile("ldmatrix.sync.aligned.m8n8.x4.trans.shared.b16 {%0,%1,%2,%3}, [%4];\n"
                                     : "=r"(b[nj][0]), "=r"(b[nj][1]), "=r"(b[nj][2]), "=r"(b[nj][3])
                                     : "r"(addr));
                    }
#pragma unroll
                    for (int mi = 0; mi < 2; mi++)
#pragma unroll
                        for (int ni = 0; ni < 4; ni++) {
                            unsigned b0 = b[ni >> 1][(ni & 1) * 2];
                            unsigned b1 = b[ni >> 1][(ni & 1) * 2 + 1];
                            asm volatile(
                                "mma.sync.aligned.m16n8k16.row.col.f32.bf16.bf16.f32 "
                                "{%0,%1,%2,%3}, {%4,%5,%6,%7}, {%8,%9}, {%0,%1,%2,%3};\n"
                                : "+f"(acc[mi][ni][0]), "+f"(acc[mi][ni][1]),
                                  "+f"(acc[mi][ni][2]), "+f"(acc[mi][ni][3])
                                : "r"(a[mi][0]), "r"(a[mi][1]), "r"(a[mi][2]), "r"(a[mi][3]),
                                  "r"(b0), "r"(b1));
                        }
                }
                __syncthreads();
                if (++buf == 3) buf = 0;
            }

            // epilogue: bias + bf16 store
#pragma unroll
            for (int mi = 0; mi < 2; mi++) {
#pragma unroll
                for (int ni = 0; ni < 4; ni++) {
                    int col = n0 + wc * 32 + ni * 8 + (lane & 3) * 2;
                    float bx = bias[col], by = bias[col + 1];
                    int row0 = m0 + wr * 32 + mi * 16 + (lane >> 2);
                    __nv_bfloat162 v0 = __floats2bfloat162_rn(acc[mi][ni][0] + bx, acc[mi][ni][1] + by);
                    __nv_bfloat162 v1 = __floats2bfloat162_rn(acc[mi][ni][2] + bx, acc[mi][ni][3] + by);
                    *(__nv_bfloat162*)(outp + (size_t)row0 * G4 + col) = v0;
                    *(__nv_bfloat162*)(outp + (size_t)(row0 + 8) * G4 + col) = v1;
                }
            }
            __threadfence();
            __syncthreads();
            if (tid == 0)
                asm volatile("red.release.gpu.global.add.u32 [%0], 1;"
                             :: "l"(&g_grpcnt[dirw][tg]) : "memory");
        }
    }

    // ===================== LSTM (clusters 0..3, R9 core + group poll) =====================
    __nv_bfloat16* Ws = (__nv_bfloat16*)smraw;                  // [512][136]
    float* gatesA = (float*)(smraw + OFF_GATES);                // [16][136] (kh=0)
    float* gatesB = gatesA + 16 * GPAD;                         // [16][136] (kh=1)

    int rank = blockIdx.x & 15;
    int dir = cid >> 1;
    int bg  = cid & 1;
    int j0  = rank * 32;

    const __nv_bfloat16* Whh = g_wb2[dir];
    const __nv_bfloat16* xw = g_xwb[dir];

    unsigned sbase = smaddr(smraw);
    unsigned stg0  = sbase + OFF_STG;
    unsigned mbar0 = sbase + OFF_MBAR;

    if (tid == 0) {
        asm volatile("mbarrier.init.shared.b64 [%0], 16;" :: "r"(mbar0) : "memory");
        asm volatile("mbarrier.init.shared.b64 [%0], 16;" :: "r"(mbar0 + 8) : "memory");
    }
    for (int c = tid; c < STG_PAR / 8; c += 512)
        ((uint2*)(smraw + OFF_STG))[c] = make_uint2(0, 0);
    for (int c = tid; c < 512 * 16; c += 512) {
        int k = c >> 4, ch = c & 15;
        int q = ch >> 2, jb = (ch & 3) * 8;
        uint4 v = *(const uint4*)(Whh + (size_t)k * G4 + q * 512 + j0 + jb);
        *(uint4*)(Ws + k * WPAD + q * 32 + jb) = v;
    }
    __syncthreads();
    asm volatile("barrier.cluster.arrive.aligned;" ::: "memory");
    asm volatile("barrier.cluster.wait.aligned;" ::: "memory");

    int kh = wid & 1;
    int ng = wid >> 1;
    int kbase = kh * 256;
    int ngc = ng * 16;
    float* gw = kh ? gatesB : gatesA;

    unsigned bfr[16][4];
#pragma unroll
    for (int kk = 0; kk < 16; kk++) {
        int k0 = kbase + kk * 16;
        unsigned addr = smaddr(Ws + (k0 + (lane & 15)) * WPAD + ngc + 8 * (lane >> 4));
        asm volatile("ldmatrix.sync.aligned.m8n8.x4.trans.shared.b16 {%0,%1,%2,%3}, [%4];\n"
                     : "=r"(bfr[kk][0]), "=r"(bfr[kk][1]), "=r"(bfr[kk][2]), "=r"(bfr[kk][3])
                     : "r"(addr));
    }

    unsigned pst[2];
#pragma unroll
    for (int i = 0; i < 2; i++) {
        unsigned tgt = (lane & 7) + 8 * i;
        unsigned r;
        asm("mapa.shared::cluster.u32 %0, %1, %2;" : "=r"(r) : "r"(stg0), "r"(tgt));
        pst[i] = r + (unsigned)(wid * STG_ROW + j0 * 2 + (lane >> 3) * 16);
    }
    unsigned pmbar = 0;
    if (wid == 0 && lane < 16)
        asm("mapa.shared::cluster.u32 %0, %1, %2;" : "=r"(pmbar) : "r"(mbar0), "r"(lane));

    int ph0 = 0, ph1 = 0;
    float cst = 0.f;

    for (int s = 0; s < TT; s++) {
        int p = s & 1;
        int t = dir ? (TT - 1 - s) : s;

        // wait for GEMM workers to finish this t-group (every 4 steps)
        if ((s & 3) == 0) {
            int gq = dir ? (127 - (s >> 2)) : (s >> 2);
            if (tid == 0) {
                unsigned v;
                for (;;) {
                    asm volatile("ld.acquire.gpu.global.u32 %0, [%1];"
                                 : "=r"(v) : "l"(&g_grpcnt[dir][gq]) : "memory");
                    if (v >= 16u) break;
                    __nanosleep(128);
                }
            }
            __syncthreads();
        }

        const __nv_bfloat16* xrow = xw + (size_t)(t * BB + bg * 16 + wid) * G4 + j0 + lane;
        float xq0 = __bfloat162float(xrow[0]);
        float xq1 = __bfloat162float(xrow[512]);
        float xq2 = __bfloat162float(xrow[1024]);
        float xq3 = __bfloat162float(xrow[1536]);

        if (s) {
            unsigned mb = mbar0 + p * 8;
            int phv = p ? ph1 : ph0;
            asm volatile(
                "{\n\t.reg .pred P;\n"
                "WL%=:\n\t"
                "mbarrier.try_wait.parity.acquire.cluster.shared::cta.b64 P, [%0], %1, 0x989680;\n\t"
                "@P bra WD%=;\n\t"
                "bra WL%=;\n"
                "WD%=:\n\t}"
                :: "r"(mb), "r"(phv) : "memory");
            if (p) ph1 ^= 1; else ph0 ^= 1;
        }

        unsigned stgp = stg0 + (unsigned)(p * STG_PAR);
        float acc[2][4];
#pragma unroll
        for (int i = 0; i < 2; i++)
#pragma unroll
            for (int j = 0; j < 4; j++) acc[i][j] = 0.f;

#pragma unroll
        for (int kk = 0; kk < 16; kk++) {
            int k0 = kbase + kk * 16;
            unsigned a[4];
            unsigned addr = stgp + (unsigned)((lane & 15) * STG_ROW + k0 * 2 + (lane >> 4) * 16);
            asm volatile("ldmatrix.sync.aligned.m8n8.x4.shared.b16 {%0,%1,%2,%3}, [%4];\n"
                         : "=r"(a[0]), "=r"(a[1]), "=r"(a[2]), "=r"(a[3]) : "r"(addr));
#pragma unroll
            for (int nt = 0; nt < 2; nt++) {
                asm volatile(
                    "mma.sync.aligned.m16n8k16.row.col.f32.bf16.bf16.f32 "
                    "{%0,%1,%2,%3}, {%4,%5,%6,%7}, {%8,%9}, {%0,%1,%2,%3};\n"
                    : "+f"(acc[nt][0]), "+f"(acc[nt][1]), "+f"(acc[nt][2]), "+f"(acc[nt][3])
                    : "r"(a[0]), "r"(a[1]), "r"(a[2]), "r"(a[3]),
                      "r"(bfr[kk][nt * 2]), "r"(bfr[kk][nt * 2 + 1]));
            }
        }

        {
            int r = lane >> 2;
            int cb = ngc + (lane & 3) * 2;
#pragma unroll
            for (int nt = 0; nt < 2; nt++) {
                *(float2*)(gw + r * GPAD + cb + nt * 8)       = make_float2(acc[nt][0], acc[nt][1]);
                *(float2*)(gw + (r + 8) * GPAD + cb + nt * 8) = make_float2(acc[nt][2], acc[nt][3]);
            }
        }
        __syncthreads();

        float h;
        {
            float gi = gatesA[wid * GPAD + lane]      + gatesB[wid * GPAD + lane]      + xq0;
            float gf = gatesA[wid * GPAD + 32 + lane] + gatesB[wid * GPAD + 32 + lane] + xq1;
            float gg = gatesA[wid * GPAD + 64 + lane] + gatesB[wid * GPAD + 64 + lane] + xq2;
            float go = gatesA[wid * GPAD + 96 + lane] + gatesB[wid * GPAD + 96 + lane] + xq3;
            float si = 0.5f * tanha(0.5f * gi) + 0.5f;
            float sf = 0.5f * tanha(0.5f * gf) + 0.5f;
            float so = 0.5f * tanha(0.5f * go) + 0.5f;
            cst = sf * cst + si * tanha(gg);
            h = so * tanha(cst);
        }
        __nv_bfloat16 hb16 = __float2bfloat16(h);
        g_hsb[(size_t)(t * BB + bg * 16 + wid) * (2 * HH) + dir * HH + j0 + lane] = hb16;

        if (s + 1 < TT) {
            unsigned hb = (unsigned)(*(unsigned short*)&hb16);
            unsigned o1 = __shfl_xor_sync(0xffffffffu, hb, 1);
            unsigned p32 = (lane & 1) ? ((hb << 16) | o1) : ((o1 << 16) | hb);
            unsigned o2 = __shfl_xor_sync(0xffffffffu, p32, 2);
            unsigned lo = (lane & 2) ? o2 : p32;
            unsigned hi = (lane & 2) ? p32 : o2;
            unsigned lo2 = __shfl_xor_sync(0xffffffffu, lo, 4);
            unsigned hi2 = __shfl_xor_sync(0xffffffffu, hi, 4);
            unsigned r0 = (lane & 4) ? lo2 : lo;
            unsigned r1 = (lane & 4) ? hi2 : hi;
            unsigned r2 = (lane & 4) ? lo : lo2;
            unsigned r3 = (lane & 4) ? hi : hi2;
            unsigned off = (unsigned)((p ^ 1) * STG_PAR);
#pragma unroll
            for (int i = 0; i < 2; i++)
                asm volatile("st.shared::cluster.v4.b32 [%0], {%1,%2,%3,%4};"
                             :: "r"(pst[i] + off), "r"(r0), "r"(r1), "r"(r2), "r"(r3) : "memory");
            __syncthreads();
            if (wid == 0 && lane < 16)
                asm volatile("mbarrier.arrive.release.cluster.shared::cluster.b64 _, [%0];"
                             :: "r"(pmbar + (unsigned)((p ^ 1) * 8)) : "memory");
        }
    }

    asm volatile("barrier.cluster.arrive.aligned;" ::: "memory");
    asm volatile("barrier.cluster.wait.aligned;" ::: "memory");
}

// ------------------------- tag projection: bf16 mma GEMM -------------------------
#define TBK 64
#define TB_STRIDE 40
#define TA_STRIDE 72
#define TA_BUF (128 * TA_STRIDE)
#define TSMEM ((1024 * TB_STRIDE + 2 * TA_BUF) * 2)

__global__ __launch_bounds__(256) void k_tag(const float* __restrict__ Wtag,
                                             const float* __restrict__ btag)
{
    extern __shared__ char tsm[];
    __nv_bfloat16* Bt = (__nv_bfloat16*)tsm;
    __nv_bfloat16* As = Bt + 1024 * TB_STRIDE;

    int tid = threadIdx.x;
    int wid = tid >> 5;
    int lane = tid & 31;
    int m0 = blockIdx.x * 128;

    for (int idx = tid; idx < 1024 * 32; idx += 256) {
        int k = idx >> 5, n = idx & 31;
        float v = (n < KK) ? Wtag[k * KK + n] : 0.f;
        Bt[k * TB_STRIDE + n] = __float2bfloat16(v);
    }

    auto loadA = [&](int buf, int k0) {
        __nv_bfloat16* Ab = As + buf * TA_BUF;
#pragma unroll
        for (int j = 0; j < 4; j++) {
            int c = tid + j * 256;
            int r = c >> 3, q = c & 7;
            unsigned dst = smaddr(Ab + r * TA_STRIDE + q * 8);
            const __nv_bfloat16* src = g_hsb + (size_t)(m0 + r) * 1024 + k0 + q * 8;
            asm volatile("cp.async.cg.shared.global [%0], [%1], 16;\n" :: "r"(dst), "l"(src));
        }
    };

    loadA(0, 0);
    asm volatile("cp.async.commit_group;\n");
    __syncthreads();

    float acc[4][4];
#pragma unroll
    for (int i = 0; i < 4; i++)
#pragma unroll
        for (int j = 0; j < 4; j++) acc[i][j] = 0.f;

    for (int kt = 0; kt < 1024 / TBK; kt++) {
        int buf = kt & 1;
        if (kt + 1 < 1024 / TBK) {
            loadA(buf ^ 1, (kt + 1) * TBK);
            asm volatile("cp.async.commit_group;\n");
            asm volatile("cp.async.wait_group 1;\n");
        } else {
            asm volatile("cp.async.wait_group 0;\n");
        }
        __syncthreads();
        __nv_bfloat16* Ab = As + buf * TA_BUF;
#pragma unroll
        for (int ks = 0; ks < 4; ks++) {
            int k0 = ks * 16;
            int kabs = kt * TBK + k0;
            unsigned a[4];
            unsigned addr = smaddr(Ab + (wid * 16 + (lane & 15)) * TA_STRIDE + k0 + 8 * (lane >> 4));
            asm volatile("ldmatrix.sync.aligned.m8n8.x4.shared.b16 {%0,%1,%2,%3}, [%4];\n"
                         : "=r"(a[0]), "=r"(a[1]), "=r"(a[2]), "=r"(a[3]) : "r"(addr));
            unsigned b[2][4];
#pragma unroll
            for (int nj = 0; nj < 2; nj++) {
                unsigned baddr = smaddr(Bt + (kabs + (lane & 15)) * TB_STRIDE + nj * 16 + 8 * (lane >> 4));
                asm volatile("ldmatrix.sync.aligned.m8n8.x4.trans.shared.b16 {%0,%1,%2,%3}, [%4];\n"
                             : "=r"(b[nj][0]), "=r"(b[nj][1]), "=r"(b[nj][2]), "=r"(b[nj][3])
                             : "r"(baddr));
            }
#pragma unroll
            for (int ni = 0; ni < 4; ni++) {
                unsigned b0 = b[ni >> 1][(ni & 1) * 2];
                unsigned b1 = b[ni >> 1][(ni & 1) * 2 + 1];
                asm volatile(
                    "mma.sync.aligned.m16n8k16.row.col.f32.bf16.bf16.f32 "
                    "{%0,%1,%2,%3}, {%4,%5,%6,%7}, {%8,%9}, {%0,%1,%2,%3};\n"
                    : "+f"(acc[ni][0]), "+f"(acc[ni][1]), "+f"(acc[ni][2]), "+f"(acc[ni][3])
                    : "r"(a[0]), "r"(a[1]), "r"(a[2]), "r"(a[3]), "r"(b0), "r"(b1));
            }
        }
        __syncthreads();
    }

#pragma unroll
    for (int ni = 0; ni < 4; ni++) {
        int col = ni * 8 + (lane & 3) * 2;
#pragma unroll
        for (int half = 0; half < 2; half++) {
            int m = m0 + wid * 16 + (lane >> 2) + half * 8;
            int b = m & 31, t = m >> 5;
            float* fo = g_feats + ((size_t)b * TT + t) * KK;
            if (col < KK)     fo[col]     = acc[ni][half * 2]     + btag[col];
            if (col + 1 < KK) fo[col + 1] = acc[ni][half * 2 + 1] + btag[col + 1];
        }
    }
}

// ------------------------- CRF NLL (one warp per sentence) -------------------------
__global__ void k_crf(const float* __restrict__ trans, const int* __restrict__ tags,
                      float* __restrict__ out)
{
    int b = blockIdx.x;
    int lane = threadIdx.x;
    float trow[KK];
    int lr = (lane < KK) ? lane : 0;
#pragma unroll
    for (int p = 0; p < KK; p++) trow[p] = trans[lr * KK + p];
    float alpha = (lane == TSTART) ? 0.f : NEGV;
    const float* fb = g_feats + (size_t)b * TT * KK;
    for (int t = 0; t < TT; t++) {
        float emit = (lane < KK) ? fb[t * KK + lane] : 0.f;
        float v[KK];
        float vmax = -1e30f;
#pragma unroll
        for (int p = 0; p < KK; p++) {
            v[p] = __shfl_sync(0xffffffffu, alpha, p) + trow[p];
            vmax = fmaxf(vmax, v[p]);
        }
        float ssum = 0.f;
#pragma unroll
        for (int p = 0; p < KK; p++) ssum += __expf(v[p] - vmax);
        float na = vmax + __logf(ssum) + emit;
        alpha = (lane < KK) ? na : NEGV;
    }
    float v = (lane < KK) ? (alpha + trans[TSTOP * KK + lane]) : -1e30f;
    float m = v;
#pragma unroll
    for (int off = 16; off; off >>= 1) m = fmaxf(m, __shfl_xor_sync(0xffffffffu, m, off));
    float e = (lane < KK) ? __expf(v - m) : 0.f;
#pragma unroll
    for (int off = 16; off; off >>= 1) e += __shfl_xor_sync(0xffffffffu, e, off);
    float logz = m + __logf(e);
    const int* tg = tags + b * TT;
    float gold = 0.f;
    for (int j = lane; j < TT + 1; j += 32) {
        int prev = (j == 0) ? TSTART : tg[j - 1];
        int nxt  = (j < TT) ? tg[j] : TSTOP;
        gold += trans[nxt * KK + prev];
        if (j < TT) gold += fb[j * KK + tg[j]];
    }
#pragma unroll
    for (int off = 16; off; off >>= 1) gold += __shfl_xor_sync(0xffffffffu, gold, off);
    if (lane == 0) out[b] = logz - gold;
}

// ------------------------- launcher -------------------------
extern "C" void kernel_launch(void* const* d_in, const int* in_sizes, int n_in,
                              void* d_out, int out_size)
{
    const int*   ids   = (const int*)  d_in[0];
    const int*   tags  = (const int*)  d_in[1];
    const float* embed = (const float*)d_in[2];
    const float* Wihf  = (const float*)d_in[3];
    const float* Whhf  = (const float*)d_in[4];
    const float* bf    = (const float*)d_in[5];
    const float* Wihb  = (const float*)d_in[6];
    const float* Whhb  = (const float*)d_in[7];
    const float* bb    = (const float*)d_in[8];
    const float* Wtag  = (const float*)d_in[9];
    const float* btag  = (const float*)d_in[10];
    const float* trans = (const float*)d_in[11];
    float* out = (float*)d_out;

    cudaFuncSetAttribute(k_tag,   cudaFuncAttributeMaxDynamicSharedMemorySize, TSMEM);
    cudaFuncSetAttribute(k_fused, cudaFuncAttributeMaxDynamicSharedMemorySize, LSM_BYTES);
    cudaFuncSetAttribute(k_fused, cudaFuncAttributeNonPortableClusterSizeAllowed, 1);

    {
        size_t nx = (size_t)MTOT * (DIN / 4);
        k_castx<<<(unsigned)((nx + 255) / 256), 256>>>(embed, ids);
        size_t nwt = 2 * NW4 + 2 * NH4;
        k_castw<<<(unsigned)((nwt + 255) / 256), 256>>>(Wihf, Wihb, Whhf, Whhb);
    }
    k_fused<<<128, 512, LSM_BYTES>>>(bf, bb);   // 8 clusters of 16: 4 LSTM + 4 workers
    k_tag<<<MTOT / 128, 256, TSMEM>>>(Wtag, btag);
    k_crf<<<BB, 32>>>(trans, tags, out);
}

// round 13
// speedup vs baseline: 1.0658x; 1.0658x over previous
#include <cuda_runtime.h>
#include <cuda_bf16.h>
#include <math.h>

#define BB 32
#define TT 512
#define DIN 1824
#define HH 512
#define G4 2048
#define KK 30
#define TSTART 28
#define TSTOP 29
#define NEGV (-10000.0f)
#define MTOT (TT*BB)            /* 16384 */

// ------------------------- device scratch -------------------------
__device__ __nv_bfloat16 g_xwb[2][(size_t)MTOT*G4];  // input proj, bf16
__device__ __nv_bfloat16 g_hsb[(size_t)MTOT*2*HH];   // [m][hf|hb] bf16, m=t*B+b
__device__ float g_feats[(size_t)BB*TT*KK];          // [b][t][k]
__device__ __nv_bfloat16 g_xb[(size_t)MTOT*DIN];     // gathered embeddings, bf16
__device__ __nv_bfloat16 g_wb[2][(size_t)DIN*G4];    // W_ih f/b, bf16
__device__ __nv_bfloat16 g_wb2[2][(size_t)HH*G4];    // W_hh f/b, bf16

__device__ __forceinline__ unsigned smaddr(const void* p)
{
    return (unsigned)__cvta_generic_to_shared(p);
}

__device__ __forceinline__ float tanha(float x)
{
    float r;
    asm("tanh.approx.f32 %0, %1;" : "=f"(r) : "f"(x));
    return r;
}

// ------------------------- cast kernels -------------------------
__global__ __launch_bounds__(256) void k_castx(const float* __restrict__ embed,
                                               const int* __restrict__ ids)
{
    size_t idx = (size_t)blockIdx.x * 256 + threadIdx.x;
    if (idx >= (size_t)MTOT * (DIN / 4)) return;
    int m = (int)(idx / (DIN / 4));
    int q = (int)(idx % (DIN / 4));
    int id = ids[(m & 31) * TT + (m >> 5)];
    float4 v = *(const float4*)(embed + (size_t)id * DIN + 4 * q);
    __nv_bfloat162 lo = __floats2bfloat162_rn(v.x, v.y);
    __nv_bfloat162 hi = __floats2bfloat162_rn(v.z, v.w);
    uint2 pk; pk.x = *(unsigned*)&lo; pk.y = *(unsigned*)&hi;
    *(uint2*)(g_xb + (size_t)m * DIN + 4 * q) = pk;
}

#define NW4 ((size_t)DIN*G4/4)
#define NH4 ((size_t)HH*G4/4)

__global__ __launch_bounds__(256) void k_castw(const float* __restrict__ f0,
                                               const float* __restrict__ f1,
                                               const float* __restrict__ f2,
                                               const float* __restrict__ f3)
{
    size_t idx = (size_t)blockIdx.x * 256 + threadIdx.x;
    const float* src; __nv_bfloat16* dst;
    if (idx < NW4)                    { src = f0; dst = g_wb[0]; }
    else if (idx < 2 * NW4)           { src = f1; dst = g_wb[1]; idx -= NW4; }
    else if (idx < 2 * NW4 + NH4)     { src = f2; dst = g_wb2[0]; idx -= 2 * NW4; }
    else if (idx < 2 * NW4 + 2 * NH4) { src = f3; dst = g_wb2[1]; idx -= 2 * NW4 + NH4; }
    else return;
    float4 v = *(const float4*)(src + 4 * idx);
    __nv_bfloat162 lo = __floats2bfloat162_rn(v.x, v.y);
    __nv_bfloat162 hi = __floats2bfloat162_rn(v.z, v.w);
    uint2 pk; pk.x = *(unsigned*)&lo; pk.y = *(unsigned*)&hi;
    *(uint2*)(dst + 4 * idx) = pk;
}

// ------------------------- input GEMM: both dirs, 3-stage cp.async, bf16 out ----------
#define BM 128
#define BN 128
#define BK 32
#define NKT (DIN / BK)   /* 57 */
#define GA_STRIDE (BK + 8)
#define GB_STRIDE (BN + 8)
#define GA_BUF (BM * GA_STRIDE)
#define GB_BUF (BK * GB_STRIDE)
#define GSMEM ((3 * (GA_BUF + GB_BUF)) * 2)

__global__ __launch_bounds__(256) void k_gemm(const float* __restrict__ bf_,
                                              const float* __restrict__ bb_)
{
    extern __shared__ char gsm[];
    __nv_bfloat16* As = (__nv_bfloat16*)gsm;
    __nv_bfloat16* Bs = As + 3 * GA_BUF;

    int dir = blockIdx.x >> 4;
    int n0 = (blockIdx.x & 15) * BN;
    const float* bias = dir ? bb_ : bf_;
    const __nv_bfloat16* A = g_xb;
    const __nv_bfloat16* Bw = g_wb[dir];
    __nv_bfloat16* out = g_xwb[dir];

    int tid = threadIdx.x;
    int wid = tid >> 5;
    int lane = tid & 31;
    int m0 = blockIdx.y * BM;
    int wm = (wid & 3) * 32;
    int wn = (wid >> 2) * 64;

    float acc[2][8][4];
#pragma unroll
    for (int i = 0; i < 2; i++)
#pragma unroll
        for (int j = 0; j < 8; j++)
#pragma unroll
            for (int r = 0; r < 4; r++) acc[i][j][r] = 0.f;

    auto loadAB = [&](int buf, int k0) {
        __nv_bfloat16* Ab = As + buf * GA_BUF;
        __nv_bfloat16* Bb = Bs + buf * GB_BUF;
#pragma unroll
        for (int j = 0; j < 2; j++) {
            int c = tid + j * 256;
            int r = c >> 2, q = c & 3;
            unsigned dst = smaddr(Ab + r * GA_STRIDE + q * 8);
            const __nv_bfloat16* src = A + (size_t)(m0 + r) * DIN + k0 + q * 8;
            asm volatile("cp.async.cg.shared.global [%0], [%1], 16;\n" :: "r"(dst), "l"(src));
        }
#pragma unroll
        for (int j = 0; j < 2; j++) {
            int c = tid + j * 256;
            int r = c >> 4, q = c & 15;
            unsigned dst = smaddr(Bb + r * GB_STRIDE + q * 8);
            const __nv_bfloat16* src = Bw + (size_t)(k0 + r) * G4 + n0 + q * 8;
            asm volatile("cp.async.cg.shared.global [%0], [%1], 16;\n" :: "r"(dst), "l"(src));
        }
    };

    loadAB(0, 0);
    asm volatile("cp.async.commit_group;\n");
    loadAB(1, BK);
    asm volatile("cp.async.commit_group;\n");

    int buf = 0;
    for (int kt = 0; kt < NKT; kt++) {
        asm volatile("cp.async.wait_group 1;\n");
        __syncthreads();
        if (kt + 2 < NKT) {
            int nb = buf + 2; if (nb >= 3) nb -= 3;
            loadAB(nb, (kt + 2) * BK);
        }
        asm volatile("cp.async.commit_group;\n");

        __nv_bfloat16* Ab = As + buf * GA_BUF;
        __nv_bfloat16* Bb = Bs + buf * GB_BUF;
#pragma unroll
        for (int ks = 0; ks < 2; ks++) {
            int k0 = ks * 16;
            unsigned a[2][4];
#pragma unroll
            for (int mi = 0; mi < 2; mi++) {
                unsigned addr = smaddr(Ab + (wm + mi * 16 + (lane & 15)) * GA_STRIDE + k0 + 8 * (lane >> 4));
                asm volatile("ldmatrix.sync.aligned.m8n8.x4.shared.b16 {%0,%1,%2,%3}, [%4];\n"
                             : "=r"(a[mi][0]), "=r"(a[mi][1]), "=r"(a[mi][2]), "=r"(a[mi][3])
                             : "r"(addr));
            }
            unsigned b[4][4];
#pragma unroll
            for (int nj = 0; nj < 4; nj++) {
                unsigned addr = smaddr(Bb + (k0 + (lane & 15)) * GB_STRIDE + wn + nj * 16 + 8 * (lane >> 4));
                asm volatile("ldmatrix.sync.aligned.m8n8.x4.trans.shared.b16 {%0,%1,%2,%3}, [%4];\n"
                             : "=r"(b[nj][0]), "=r"(b[nj][1]), "=r"(b[nj][2]), "=r"(b[nj][3])
                             : "r"(addr));
            }
#pragma unroll
            for (int mi = 0; mi < 2; mi++)
#pragma unroll
                for (int ni = 0; ni < 8; ni++) {
                    unsigned b0 = b[ni >> 1][(ni & 1) * 2];
                    unsigned b1 = b[ni >> 1][(ni & 1) * 2 + 1];
                    asm volatile(
                        "mma.sync.aligned.m16n8k16.row.col.f32.bf16.bf16.f32 "
                        "{%0,%1,%2,%3}, {%4,%5,%6,%7}, {%8,%9}, {%0,%1,%2,%3};\n"
                        : "+f"(acc[mi][ni][0]), "+f"(acc[mi][ni][1]),
                          "+f"(acc[mi][ni][2]), "+f"(acc[mi][ni][3])
                        : "r"(a[mi][0]), "r"(a[mi][1]), "r"(a[mi][2]), "r"(a[mi][3]),
                          "r"(b0), "r"(b1));
                }
        }
        __syncthreads();
        if (++buf == 3) buf = 0;
    }

#pragma unroll
    for (int mi = 0; mi < 2; mi++) {
#pragma unroll
        for (int ni = 0; ni < 8; ni++) {
            int col = n0 + wn + ni * 8 + (lane & 3) * 2;
            float bx = bias[col], by = bias[col + 1];
            int row0 = m0 + wm + mi * 16 + (lane >> 2);
            __nv_bfloat162 v0 = __floats2bfloat162_rn(acc[mi][ni][0] + bx, acc[mi][ni][1] + by);
            __nv_bfloat162 v1 = __floats2bfloat162_rn(acc[mi][ni][2] + bx, acc[mi][ni][3] + by);
            *(__nv_bfloat162*)(out + (size_t)row0 * G4 + col) = v0;
            *(__nv_bfloat162*)(out + (size_t)(row0 + 8) * G4 + col) = v1;
        }
    }
}

// --------- LSTM: 2 clusters (one per dir), 2 interleaved bg streams, R9 warp decomp ---
// 16 CTAs/cluster, 512 thr, warps kh(2) x ng(8): n16, K=256 each — preserves A-fragment
// reuse (128KB/step SMEM reads). Streams bg0/bg1 alternate so each stream's DSMEM
// exchange + mbar propagation is hidden under the other stream's compute. Both streams
// share the resident W slice + B register fragments; separate staging/mbar/phase/c.
#define WPAD 136
#define SPAD 520
#define GPAD 136
#define STG_ROW   (SPAD*2)              /* 1040 B */
#define STG_PAR   (16*STG_ROW)          /* 16640 B */
#define OFF_STG   (512*WPAD*2)          /* 139264 */
#define OFF_GATES (OFF_STG + 4*STG_PAR) /* 205824 */
#define OFF_MBAR  (OFF_GATES + 2*16*GPAD*4)  /* 223232 */
#define LSM_BYTES (OFF_MBAR + 64)       /* 223296 */

__global__ __launch_bounds__(512, 1) __cluster_dims__(16, 1, 1)
void k_lstm4(void)
{
    extern __shared__ char smraw[];
    __nv_bfloat16* Ws = (__nv_bfloat16*)smraw;                  // [512][136]
    float* gatesA = (float*)(smraw + OFF_GATES);                // [16][136] (kh=0)
    float* gatesB = gatesA + 16 * GPAD;                         // [16][136] (kh=1)

    int tid = threadIdx.x;
    int wid = tid >> 5;
    int lane = tid & 31;
    int dir = blockIdx.x >> 4;
    int rank = blockIdx.x & 15;
    int j0 = rank * 32;

    const __nv_bfloat16* Whh = g_wb2[dir];
    const __nv_bfloat16* xw = g_xwb[dir];

    unsigned sbase = smaddr(smraw);
    unsigned stg0  = sbase + OFF_STG;
    unsigned mbar0 = sbase + OFF_MBAR;

    if (tid == 0) {
#pragma unroll
        for (int i = 0; i < 4; i++)
            asm volatile("mbarrier.init.shared.b64 [%0], 16;" :: "r"(mbar0 + i * 8) : "memory");
    }
    // zero parity-0 staging of both streams (h0 = 0)
    for (int c = tid; c < STG_PAR / 8; c += 512) {
        ((uint2*)(smraw + OFF_STG))[c] = make_uint2(0, 0);
        ((uint2*)(smraw + OFF_STG + 2 * STG_PAR))[c] = make_uint2(0, 0);
    }
    for (int c = tid; c < 512 * 16; c += 512) {
        int k = c >> 4, ch = c & 15;
        int q = ch >> 2, jb = (ch & 3) * 8;
        uint4 v = *(const uint4*)(Whh + (size_t)k * G4 + q * 512 + j0 + jb);
        *(uint4*)(Ws + k * WPAD + q * 32 + jb) = v;
    }
    __syncthreads();
    asm volatile("barrier.cluster.arrive.aligned;" ::: "memory");
    asm volatile("barrier.cluster.wait.aligned;" ::: "memory");

    int kh = wid & 1;
    int ng = wid >> 1;
    int kbase = kh * 256;
    int ngc = ng * 16;
    float* gw = kh ? gatesB : gatesA;

    unsigned bfr[16][4];
#pragma unroll
    for (int kk = 0; kk < 16; kk++) {
        int k0 = kbase + kk * 16;
        unsigned addr = smaddr(Ws + (k0 + (lane & 15)) * WPAD + ngc + 8 * (lane >> 4));
        asm volatile("ldmatrix.sync.aligned.m8n8.x4.trans.shared.b16 {%0,%1,%2,%3}, [%4];\n"
                     : "=r"(bfr[kk][0]), "=r"(bfr[kk][1]), "=r"(bfr[kk][2]), "=r"(bfr[kk][3])
                     : "r"(addr));
    }

    // DSMEM store targets: 16B chunk (lane>>3) of row wid, to ranks (lane&7), (lane&7)+8
    unsigned pst[2];
#pragma unroll
    for (int i = 0; i < 2; i++) {
        unsigned tgt = (lane & 7) + 8 * i;
        unsigned r;
        asm("mapa.shared::cluster.u32 %0, %1, %2;" : "=r"(r) : "r"(stg0), "r"(tgt));
        pst[i] = r + (unsigned)(wid * STG_ROW + j0 * 2 + (lane >> 3) * 16);
    }
    unsigned pmbar = 0;
    if (wid == 0 && lane < 16)
        asm("mapa.shared::cluster.u32 %0, %1, %2;" : "=r"(pmbar) : "r"(mbar0), "r"(lane));

    int ph[4] = {0, 0, 0, 0};       // phase per (stream*2 + parity)
    float cst[2] = {0.f, 0.f};      // c-state per stream, thread=(batch wid, dim lane)

    for (int s = 0; s < TT; s++) {
        int p = s & 1;
        int t = dir ? (TT - 1 - s) : s;

        // prefetch xw for both streams (LDGs issued before any waiting)
        float xq[2][4];
#pragma unroll
        for (int str = 0; str < 2; str++) {
            const __nv_bfloat16* xrow = xw + (size_t)(t * BB + str * 16 + wid) * G4 + j0 + lane;
            xq[str][0] = __bfloat162float(xrow[0]);
            xq[str][1] = __bfloat162float(xrow[512]);
            xq[str][2] = __bfloat162float(xrow[1024]);
            xq[str][3] = __bfloat162float(xrow[1536]);
        }

#pragma unroll
        for (int str = 0; str < 2; str++) {
            int mi = str * 2 + p;
            if (s) {
                unsigned mb = mbar0 + (unsigned)(mi * 8);
                asm volatile(
                    "{\n\t.reg .pred P;\n"
                    "WL%=:\n\t"
                    "mbarrier.try_wait.parity.acquire.cluster.shared::cta.b64 P, [%0], %1, 0x989680;\n\t"
                    "@P bra WD%=;\n\t"
                    "bra WL%=;\n"
                    "WD%=:\n\t}"
                    :: "r"(mb), "r"(ph[mi]) : "memory");
                ph[mi] ^= 1;
            }

            unsigned stgp = stg0 + (unsigned)((str * 2 + p) * STG_PAR);
            float acc[2][4];
#pragma unroll
            for (int i = 0; i < 2; i++)
#pragma unroll
                for (int j = 0; j < 4; j++) acc[i][j] = 0.f;

#pragma unroll
            for (int kk = 0; kk < 16; kk++) {
                int k0 = kbase + kk * 16;
                unsigned a[4];
                unsigned addr = stgp + (unsigned)((lane & 15) * STG_ROW + k0 * 2 + (lane >> 4) * 16);
                asm volatile("ldmatrix.sync.aligned.m8n8.x4.shared.b16 {%0,%1,%2,%3}, [%4];\n"
                             : "=r"(a[0]), "=r"(a[1]), "=r"(a[2]), "=r"(a[3]) : "r"(addr));
#pragma unroll
                for (int nt = 0; nt < 2; nt++) {
                    asm volatile(
                        "mma.sync.aligned.m16n8k16.row.col.f32.bf16.bf16.f32 "
                        "{%0,%1,%2,%3}, {%4,%5,%6,%7}, {%8,%9}, {%0,%1,%2,%3};\n"
                        : "+f"(acc[nt][0]), "+f"(acc[nt][1]), "+f"(acc[nt][2]), "+f"(acc[nt][3])
                        : "r"(a[0]), "r"(a[1]), "r"(a[2]), "r"(a[3]),
                          "r"(bfr[kk][nt * 2]), "r"(bfr[kk][nt * 2 + 1]));
                }
            }

            // kh halves store to separate buffers; single sync; add at gate math
            {
                int r = lane >> 2;
                int cb = ngc + (lane & 3) * 2;
#pragma unroll
                for (int nt = 0; nt < 2; nt++) {
                    *(float2*)(gw + r * GPAD + cb + nt * 8)       = make_float2(acc[nt][0], acc[nt][1]);
                    *(float2*)(gw + (r + 8) * GPAD + cb + nt * 8) = make_float2(acc[nt][2], acc[nt][3]);
                }
            }
            __syncthreads();

            float h;
            {
                float gi = gatesA[wid * GPAD + lane]      + gatesB[wid * GPAD + lane]      + xq[str][0];
                float gf = gatesA[wid * GPAD + 32 + lane] + gatesB[wid * GPAD + 32 + lane] + xq[str][1];
                float gg = gatesA[wid * GPAD + 64 + lane] + gatesB[wid * GPAD + 64 + lane] + xq[str][2];
                float go = gatesA[wid * GPAD + 96 + lane] + gatesB[wid * GPAD + 96 + lane] + xq[str][3];
                float si = 0.5f * tanha(0.5f * gi) + 0.5f;
                float sf = 0.5f * tanha(0.5f * gf) + 0.5f;
                float so = 0.5f * tanha(0.5f * go) + 0.5f;
                cst[str] = sf * cst[str] + si * tanha(gg);
                h = so * tanha(cst[str]);
            }
            __nv_bfloat16 hb16 = __float2bfloat16(h);
            g_hsb[(size_t)(t * BB + str * 16 + wid) * (2 * HH) + dir * HH + j0 + lane] = hb16;

            if (s + 1 < TT) {
                unsigned hb = (unsigned)(*(unsigned short*)&hb16);
                unsigned o1 = __shfl_xor_sync(0xffffffffu, hb, 1);
                unsigned p32 = (lane & 1) ? ((hb << 16) | o1) : ((o1 << 16) | hb);
                unsigned o2 = __shfl_xor_sync(0xffffffffu, p32, 2);
                unsigned lo = (lane & 2) ? o2 : p32;
                unsigned hi = (lane & 2) ? p32 : o2;
                unsigned lo2 = __shfl_xor_sync(0xffffffffu, lo, 4);
                unsigned hi2 = __shfl_xor_sync(0xffffffffu, hi, 4);
                unsigned r0 = (lane & 4) ? lo2 : lo;
                unsigned r1 = (lane & 4) ? hi2 : hi;
                unsigned r2 = (lane & 4) ? lo : lo2;
                unsigned r3 = (lane & 4) ? hi : hi2;
                unsigned off = (unsigned)((str * 2 + (p ^ 1)) * STG_PAR);
#pragma unroll
                for (int i = 0; i < 2; i++)
                    asm volatile("st.shared::cluster.v4.b32 [%0], {%1,%2,%3,%4};"
                                 :: "r"(pst[i] + off), "r"(r0), "r"(r1), "r"(r2), "r"(r3) : "memory");
                __syncthreads();
                if (wid == 0 && lane < 16)
                    asm volatile("mbarrier.arrive.release.cluster.shared::cluster.b64 _, [%0];"
                                 :: "r"(pmbar + (unsigned)((str * 2 + (p ^ 1)) * 8)) : "memory");
            } else {
                __syncthreads();
            }
        }
    }

    asm volatile("barrier.cluster.arrive.aligned;" ::: "memory");
    asm volatile("barrier.cluster.wait.aligned;" ::: "memory");
}

// ------------------------- tag projection: bf16 mma GEMM -------------------------
#define TBK 64
#define TB_STRIDE 40
#define TA_STRIDE 72
#define TA_BUF (128 * TA_STRIDE)
#define TSMEM ((1024 * TB_STRIDE + 2 * TA_BUF) * 2)

__global__ __launch_bounds__(256) void k_tag(const float* __restrict__ Wtag,
                                             const float* __restrict__ btag)
{
    extern __shared__ char tsm[];
    __nv_bfloat16* Bt = (__nv_bfloat16*)tsm;
    __nv_bfloat16* As = Bt + 1024 * TB_STRIDE;

    int tid = threadIdx.x;
    int wid = tid >> 5;
    int lane = tid & 31;
    int m0 = blockIdx.x * 128;

    for (int idx = tid; idx < 1024 * 32; idx += 256) {
        int k = idx >> 5, n = idx & 31;
        float v = (n < KK) ? Wtag[k * KK + n] : 0.f;
        Bt[k * TB_STRIDE + n] = __float2bfloat16(v);
    }

    auto loadA = [&](int buf, int k0) {
        __nv_bfloat16* Ab = As + buf * TA_BUF;
#pragma unroll
        for (int j = 0; j < 4; j++) {
            int c = tid + j * 256;
            int r = c >> 3, q = c & 7;
            unsigned dst = smaddr(Ab + r * TA_STRIDE + q * 8);
            const __nv_bfloat16* src = g_hsb + (size_t)(m0 + r) * 1024 + k0 + q * 8;
            asm volatile("cp.async.cg.shared.global [%0], [%1], 16;\n" :: "r"(dst), "l"(src));
        }
    };

    loadA(0, 0);
    asm volatile("cp.async.commit_group;\n");
    __syncthreads();

    float acc[4][4];
#pragma unroll
    for (int i = 0; i < 4; i++)
#pragma unroll
        for (int j = 0; j < 4; j++) acc[i][j] = 0.f;

    for (int kt = 0; kt < 1024 / TBK; kt++) {
        int buf = kt & 1;
        if (kt + 1 < 1024 / TBK) {
            loadA(buf ^ 1, (kt + 1) * TBK);
            asm volatile("cp.async.commit_group;\n");
            asm volatile("cp.async.wait_group 1;\n");
        } else {
            asm volatile("cp.async.wait_group 0;\n");
        }
        __syncthreads();
        __nv_bfloat16* Ab = As + buf * TA_BUF;
#pragma unroll
        for (int ks = 0; ks < 4; ks++) {
            int k0 = ks * 16;
            int kabs = kt * TBK + k0;
            unsigned a[4];
            unsigned addr = smaddr(Ab + (wid * 16 + (lane & 15)) * TA_STRIDE + k0 + 8 * (lane >> 4));
            asm volatile("ldmatrix.sync.aligned.m8n8.x4.shared.b16 {%0,%1,%2,%3}, [%4];\n"
                         : "=r"(a[0]), "=r"(a[1]), "=r"(a[2]), "=r"(a[3]) : "r"(addr));
            unsigned b[2][4];
#pragma unroll
            for (int nj = 0; nj < 2; nj++) {
                unsigned baddr = smaddr(Bt + (kabs + (lane & 15)) * TB_STRIDE + nj * 16 + 8 * (lane >> 4));
                asm volatile("ldmatrix.sync.aligned.m8n8.x4.trans.shared.b16 {%0,%1,%2,%3}, [%4];\n"
                             : "=r"(b[nj][0]), "=r"(b[nj][1]), "=r"(b[nj][2]), "=r"(b[nj][3])
                             : "r"(baddr));
            }
#pragma unroll
            for (int ni = 0; ni < 4; ni++) {
                unsigned b0 = b[ni >> 1][(ni & 1) * 2];
                unsigned b1 = b[ni >> 1][(ni & 1) * 2 + 1];
                asm volatile(
                    "mma.sync.aligned.m16n8k16.row.col.f32.bf16.bf16.f32 "
                    "{%0,%1,%2,%3}, {%4,%5,%6,%7}, {%8,%9}, {%0,%1,%2,%3};\n"
                    : "+f"(acc[ni][0]), "+f"(acc[ni][1]), "+f"(acc[ni][2]), "+f"(acc[ni][3])
                    : "r"(a[0]), "r"(a[1]), "r"(a[2]), "r"(a[3]), "r"(b0), "r"(b1));
            }
        }
        __syncthreads();
    }

#pragma unroll
    for (int ni = 0; ni < 4; ni++) {
        int col = ni * 8 + (lane & 3) * 2;
#pragma unroll
        for (int half = 0; half < 2; half++) {
            int m = m0 + wid * 16 + (lane >> 2) + half * 8;
            int b = m & 31, t = m >> 5;
            float* fo = g_feats + ((size_t)b * TT + t) * KK;
            if (col < KK)     fo[col]     = acc[ni][half * 2]     + btag[col];
            if (col + 1 < KK) fo[col + 1] = acc[ni][half * 2 + 1] + btag[col + 1];
        }
    }
}

// ------------------------- CRF NLL (one warp per sentence) -------------------------
__global__ void k_crf(const float* __restrict__ trans, const int* __restrict__ tags,
                      float* __restrict__ out)
{
    int b = blockIdx.x;
    int lane = threadIdx.x;
    float trow[KK];
    int lr = (lane < KK) ? lane : 0;
#pragma unroll
    for (int p = 0; p < KK; p++) trow[p] = trans[lr * KK + p];
    float alpha = (lane == TSTART) ? 0.f : NEGV;
    const float* fb = g_feats + (size_t)b * TT * KK;
    for (int t = 0; t < TT; t++) {
        float emit = (lane < KK) ? fb[t * KK + lane] : 0.f;
        float v[KK];
        float vmax = -1e30f;
#pragma unroll
        for (int p = 0; p < KK; p++) {
            v[p] = __shfl_sync(0xffffffffu, alpha, p) + trow[p];
            vmax = fmaxf(vmax, v[p]);
        }
        float ssum = 0.f;
#pragma unroll
        for (int p = 0; p < KK; p++) ssum += __expf(v[p] - vmax);
        float na = vmax + __logf(ssum) + emit;
        alpha = (lane < KK) ? na : NEGV;
    }
    float v = (lane < KK) ? (alpha + trans[TSTOP * KK + lane]) : -1e30f;
    float m = v;
#pragma unroll
    for (int off = 16; off; off >>= 1) m = fmaxf(m, __shfl_xor_sync(0xffffffffu, m, off));
    float e = (lane < KK) ? __expf(v - m) : 0.f;
#pragma unroll
    for (int off = 16; off; off >>= 1) e += __shfl_xor_sync(0xffffffffu, e, off);
    float logz = m + __logf(e);
    const int* tg = tags + b * TT;
    float gold = 0.f;
    for (int j = lane; j < TT + 1; j += 32) {
        int prev = (j == 0) ? TSTART : tg[j - 1];
        int nxt  = (j < TT) ? tg[j] : TSTOP;
        gold += trans[nxt * KK + prev];
        if (j < TT) gold += fb[j * KK + tg[j]];
    }
#pragma unroll
    for (int off = 16; off; off >>= 1) gold += __shfl_xor_sync(0xffffffffu, gold, off);
    if (lane == 0) out[b] = logz - gold;
}

// ------------------------- launcher -------------------------
extern "C" void kernel_launch(void* const* d_in, const int* in_sizes, int n_in,
                              void* d_out, int out_size)
{
    const int*   ids   = (const int*)  d_in[0];
    const int*   tags  = (const int*)  d_in[1];
    const float* embed = (const float*)d_in[2];
    const float* Wihf  = (const float*)d_in[3];
    const float* Whhf  = (const float*)d_in[4];
    const float* bf    = (const float*)d_in[5];
    const float* Wihb  = (const float*)d_in[6];
    const float* Whhb  = (const float*)d_in[7];
    const float* bb    = (const float*)d_in[8];
    const float* Wtag  = (const float*)d_in[9];
    const float* btag  = (const float*)d_in[10];
    const float* trans = (const float*)d_in[11];
    float* out = (float*)d_out;

    cudaFuncSetAttribute(k_gemm, cudaFuncAttributeMaxDynamicSharedMemorySize, GSMEM);
    cudaFuncSetAttribute(k_tag,  cudaFuncAttributeMaxDynamicSharedMemorySize, TSMEM);
    cudaFuncSetAttribute(k_lstm4, cudaFuncAttributeMaxDynamicSharedMemorySize, LSM_BYTES);
    cudaFuncSetAttribute(k_lstm4, cudaFuncAttributeNonPortableClusterSizeAllowed, 1);

    {
        size_t nx = (size_t)MTOT * (DIN / 4);
        k_castx<<<(unsigned)((nx + 255) / 256), 256>>>(embed, ids);
        size_t nwt = 2 * NW4 + 2 * NH4;
        k_castw<<<(unsigned)((nwt + 255) / 256), 256>>>(Wihf, Wihb, Whhf, Whhb);
    }
    k_gemm<<<dim3(32, MTOT / BM), 256, GSMEM>>>(bf, bb);
    k_lstm4<<<32, 512, LSM_BYTES>>>();
    k_tag<<<MTOT / 128, 256, TSMEM>>>(Wtag, btag);
    k_crf<<<BB, 32>>>(trans, tags, out);
}

// round 14
// speedup vs baseline: 1.4625x; 1.3722x over previous
#include <cuda_runtime.h>
#include <cuda_bf16.h>
#include <math.h>

#define BB 32
#define TT 512
#define DIN 1824
#define HH 512
#define G4 2048
#define KK 30
#define TSTART 28
#define TSTOP 29
#define NEGV (-10000.0f)
#define MTOT (TT*BB)            /* 16384 */

// ------------------------- device scratch -------------------------
__device__ __nv_bfloat16 g_xwb[2][(size_t)MTOT*G4];  // input proj, bf16
__device__ __nv_bfloat16 g_hsb[(size_t)MTOT*2*HH];   // [m][hf|hb] bf16, m=t*B+b
__device__ float g_feats[(size_t)BB*TT*KK];          // [b][t][k]
__device__ __nv_bfloat16 g_xb[(size_t)MTOT*DIN];     // gathered embeddings, bf16
__device__ __nv_bfloat16 g_wb[2][(size_t)DIN*G4];    // W_ih f/b, bf16
__device__ __nv_bfloat16 g_wb2[2][(size_t)HH*G4];    // W_hh f/b, bf16

__device__ __forceinline__ unsigned smaddr(const void* p)
{
    return (unsigned)__cvta_generic_to_shared(p);
}

__device__ __forceinline__ float tanha(float x)
{
    float r;
    asm("tanh.approx.f32 %0, %1;" : "=f"(r) : "f"(x));
    return r;
}

// ------------------------- cast kernels -------------------------
__global__ __launch_bounds__(256) void k_castx(const float* __restrict__ embed,
                                               const int* __restrict__ ids)
{
    size_t idx = (size_t)blockIdx.x * 256 + threadIdx.x;
    if (idx >= (size_t)MTOT * (DIN / 4)) return;
    int m = (int)(idx / (DIN / 4));
    int q = (int)(idx % (DIN / 4));
    int id = ids[(m & 31) * TT + (m >> 5)];
    float4 v = *(const float4*)(embed + (size_t)id * DIN + 4 * q);
    __nv_bfloat162 lo = __floats2bfloat162_rn(v.x, v.y);
    __nv_bfloat162 hi = __floats2bfloat162_rn(v.z, v.w);
    uint2 pk; pk.x = *(unsigned*)&lo; pk.y = *(unsigned*)&hi;
    *(uint2*)(g_xb + (size_t)m * DIN + 4 * q) = pk;
}

#define NW4 ((size_t)DIN*G4/4)
#define NH4 ((size_t)HH*G4/4)

__global__ __launch_bounds__(256) void k_castw(const float* __restrict__ f0,
                                               const float* __restrict__ f1,
                                               const float* __restrict__ f2,
                                               const float* __restrict__ f3)
{
    size_t idx = (size_t)blockIdx.x * 256 + threadIdx.x;
    const float* src; __nv_bfloat16* dst;
    if (idx < NW4)                    { src = f0; dst = g_wb[0]; }
    else if (idx < 2 * NW4)           { src = f1; dst = g_wb[1]; idx -= NW4; }
    else if (idx < 2 * NW4 + NH4)     { src = f2; dst = g_wb2[0]; idx -= 2 * NW4; }
    else if (idx < 2 * NW4 + 2 * NH4) { src = f3; dst = g_wb2[1]; idx -= 2 * NW4 + NH4; }
    else return;
    float4 v = *(const float4*)(src + 4 * idx);
    __nv_bfloat162 lo = __floats2bfloat162_rn(v.x, v.y);
    __nv_bfloat162 hi = __floats2bfloat162_rn(v.z, v.w);
    uint2 pk; pk.x = *(unsigned*)&lo; pk.y = *(unsigned*)&hi;
    *(uint2*)(dst + 4 * idx) = pk;
}

// ----------- input GEMM: BM128 x BN256 x BK32, warp tile 64x64, 3-stage cp.async ------
#define BM 128
#define BN 256
#define BK 32
#define NKT (DIN / BK)   /* 57 */
#define GA_STRIDE (BK + 8)               /* 40 */
#define GB_STRIDE (BN + 8)               /* 264 */
#define GA_BUF (BM * GA_STRIDE)          /* 5120 */
#define GB_BUF (BK * GB_STRIDE)          /* 8448 */
#define GSMEM ((3 * (GA_BUF + GB_BUF)) * 2)   /* 81408 B */

__global__ __launch_bounds__(256) void k_gemm(const float* __restrict__ bf_,
                                              const float* __restrict__ bb_)
{
    extern __shared__ char gsm[];
    __nv_bfloat16* As = (__nv_bfloat16*)gsm;          // [3][128][40]
    __nv_bfloat16* Bs = As + 3 * GA_BUF;              // [3][32][264]

    int dir = blockIdx.x >> 3;
    int n0 = (blockIdx.x & 7) * BN;
    const float* bias = dir ? bb_ : bf_;
    const __nv_bfloat16* A = g_xb;
    const __nv_bfloat16* Bw = g_wb[dir];
    __nv_bfloat16* out = g_xwb[dir];

    int tid = threadIdx.x;
    int wid = tid >> 5;
    int lane = tid & 31;
    int m0 = blockIdx.y * BM;
    int wm = (wid & 1) * 64;       // 2 warp rows
    int wn = (wid >> 1) * 64;      // 4 warp cols

    float acc[4][8][4];
#pragma unroll
    for (int i = 0; i < 4; i++)
#pragma unroll
        for (int j = 0; j < 8; j++)
#pragma unroll
            for (int r = 0; r < 4; r++) acc[i][j][r] = 0.f;

    auto loadAB = [&](int buf, int k0) {
        __nv_bfloat16* Ab = As + buf * GA_BUF;
        __nv_bfloat16* Bb = Bs + buf * GB_BUF;
#pragma unroll
        for (int j = 0; j < 2; j++) {           // A: 128x32 = 512 16B chunks
            int c = tid + j * 256;
            int r = c >> 2, q = c & 3;
            unsigned dst = smaddr(Ab + r * GA_STRIDE + q * 8);
            const __nv_bfloat16* src = A + (size_t)(m0 + r) * DIN + k0 + q * 8;
            asm volatile("cp.async.cg.shared.global [%0], [%1], 16;\n" :: "r"(dst), "l"(src));
        }
#pragma unroll
        for (int j = 0; j < 4; j++) {           // B: 32x256 = 1024 16B chunks
            int c = tid + j * 256;
            int r = c >> 5, q = c & 31;
            unsigned dst = smaddr(Bb + r * GB_STRIDE + q * 8);
            const __nv_bfloat16* src = Bw + (size_t)(k0 + r) * G4 + n0 + q * 8;
            asm volatile("cp.async.cg.shared.global [%0], [%1], 16;\n" :: "r"(dst), "l"(src));
        }
    };

    loadAB(0, 0);
    asm volatile("cp.async.commit_group;\n");
    loadAB(1, BK);
    asm volatile("cp.async.commit_group;\n");

    int buf = 0;
    for (int kt = 0; kt < NKT; kt++) {
        asm volatile("cp.async.wait_group 1;\n");
        __syncthreads();
        if (kt + 2 < NKT) {
            int nb = buf + 2; if (nb >= 3) nb -= 3;
            loadAB(nb, (kt + 2) * BK);
        }
        asm volatile("cp.async.commit_group;\n");

        __nv_bfloat16* Ab = As + buf * GA_BUF;
        __nv_bfloat16* Bb = Bs + buf * GB_BUF;
#pragma unroll
        for (int ks = 0; ks < 2; ks++) {
            int k0 = ks * 16;
            unsigned a[4][4];
#pragma unroll
            for (int mi = 0; mi < 4; mi++) {
                unsigned addr = smaddr(Ab + (wm + mi * 16 + (lane & 15)) * GA_STRIDE + k0 + 8 * (lane >> 4));
                asm volatile("ldmatrix.sync.aligned.m8n8.x4.shared.b16 {%0,%1,%2,%3}, [%4];\n"
                             : "=r"(a[mi][0]), "=r"(a[mi][1]), "=r"(a[mi][2]), "=r"(a[mi][3])
                             : "r"(addr));
            }
            unsigned b[4][4];
#pragma unroll
            for (int nj = 0; nj < 4; nj++) {
                unsigned addr = smaddr(Bb + (k0 + (lane & 15)) * GB_STRIDE + wn + nj * 16 + 8 * (lane >> 4));
                asm volatile("ldmatrix.sync.aligned.m8n8.x4.trans.shared.b16 {%0,%1,%2,%3}, [%4];\n"
                             : "=r"(b[nj][0]), "=r"(b[nj][1]), "=r"(b[nj][2]), "=r"(b[nj][3])
                             : "r"(addr));
            }
#pragma unroll
            for (int mi = 0; mi < 4; mi++)
#pragma unroll
                for (int ni = 0; ni < 8; ni++) {
                    unsigned b0 = b[ni >> 1][(ni & 1) * 2];
                    unsigned b1 = b[ni >> 1][(ni & 1) * 2 + 1];
                    asm volatile(
                        "mma.sync.aligned.m16n8k16.row.col.f32.bf16.bf16.f32 "
                        "{%0,%1,%2,%3}, {%4,%5,%6,%7}, {%8,%9}, {%0,%1,%2,%3};\n"
                        : "+f"(acc[mi][ni][0]), "+f"(acc[mi][ni][1]),
                          "+f"(acc[mi][ni][2]), "+f"(acc[mi][ni][3])
                        : "r"(a[mi][0]), "r"(a[mi][1]), "r"(a[mi][2]), "r"(a[mi][3]),
                          "r"(b0), "r"(b1));
                }
        }
        __syncthreads();
        if (++buf == 3) buf = 0;
    }

#pragma unroll
    for (int mi = 0; mi < 4; mi++) {
#pragma unroll
        for (int ni = 0; ni < 8; ni++) {
            int col = n0 + wn + ni * 8 + (lane & 3) * 2;
            float bx = bias[col], by = bias[col + 1];
            int row0 = m0 + wm + mi * 16 + (lane >> 2);
            __nv_bfloat162 v0 = __floats2bfloat162_rn(acc[mi][ni][0] + bx, acc[mi][ni][1] + by);
            __nv_bfloat162 v1 = __floats2bfloat162_rn(acc[mi][ni][2] + bx, acc[mi][ni][3] + by);
            *(__nv_bfloat162*)(out + (size_t)row0 * G4 + col) = v0;
            *(__nv_bfloat162*)(out + (size_t)(row0 + 8) * G4 + col) = v1;
        }
    }
}

// ------------------------- LSTM: R9 exact (4 clusters x 16 CTAs, dual gates) ----------
#define WPAD 136
#define SPAD 520
#define GPAD 136
#define STG_ROW   (SPAD*2)              /* 1040 B */
#define STG_PAR   (16*STG_ROW)          /* 16640 B */
#define OFF_STG   (512*WPAD*2)          /* 139264 */
#define OFF_GATES (OFF_STG + 2*STG_PAR) /* 172544 */
#define OFF_MBAR  (OFF_GATES + 2*16*GPAD*4)
#define LSM_BYTES (OFF_MBAR + 64)

__global__ __launch_bounds__(512, 1) __cluster_dims__(16, 1, 1)
void k_lstm2(void)
{
    extern __shared__ char smraw[];
    __nv_bfloat16* Ws = (__nv_bfloat16*)smraw;                  // [512][136]
    float* gatesA = (float*)(smraw + OFF_GATES);                // [16][136] (kh=0)
    float* gatesB = gatesA + 16 * GPAD;                         // [16][136] (kh=1)

    int tid = threadIdx.x;
    int wid = tid >> 5;
    int lane = tid & 31;
    int cid = blockIdx.x >> 4;
    int rank = blockIdx.x & 15;
    int dir = cid >> 1;
    int bg  = cid & 1;
    int j0  = rank * 32;

    const __nv_bfloat16* Whh = g_wb2[dir];
    const __nv_bfloat16* xw = g_xwb[dir];

    unsigned sbase = smaddr(smraw);
    unsigned stg0  = sbase + OFF_STG;
    unsigned mbar0 = sbase + OFF_MBAR;

    if (tid == 0) {
        asm volatile("mbarrier.init.shared.b64 [%0], 16;" :: "r"(mbar0) : "memory");
        asm volatile("mbarrier.init.shared.b64 [%0], 16;" :: "r"(mbar0 + 8) : "memory");
    }
    for (int c = tid; c < STG_PAR / 8; c += 512)
        ((uint2*)(smraw + OFF_STG))[c] = make_uint2(0, 0);
    for (int c = tid; c < 512 * 16; c += 512) {
        int k = c >> 4, ch = c & 15;
        int q = ch >> 2, jb = (ch & 3) * 8;
        uint4 v = *(const uint4*)(Whh + (size_t)k * G4 + q * 512 + j0 + jb);
        *(uint4*)(Ws + k * WPAD + q * 32 + jb) = v;
    }
    __syncthreads();
    asm volatile("barrier.cluster.arrive.aligned;" ::: "memory");
    asm volatile("barrier.cluster.wait.aligned;" ::: "memory");

    int kh = wid & 1;
    int ng = wid >> 1;
    int kbase = kh * 256;
    int ngc = ng * 16;
    float* gw = kh ? gatesB : gatesA;

    unsigned bfr[16][4];
#pragma unroll
    for (int kk = 0; kk < 16; kk++) {
        int k0 = kbase + kk * 16;
        unsigned addr = smaddr(Ws + (k0 + (lane & 15)) * WPAD + ngc + 8 * (lane >> 4));
        asm volatile("ldmatrix.sync.aligned.m8n8.x4.trans.shared.b16 {%0,%1,%2,%3}, [%4];\n"
                     : "=r"(bfr[kk][0]), "=r"(bfr[kk][1]), "=r"(bfr[kk][2]), "=r"(bfr[kk][3])
                     : "r"(addr));
    }

    unsigned pst[2];
#pragma unroll
    for (int i = 0; i < 2; i++) {
        unsigned tgt = (lane & 7) + 8 * i;
        unsigned r;
        asm("mapa.shared::cluster.u32 %0, %1, %2;" : "=r"(r) : "r"(stg0), "r"(tgt));
        pst[i] = r + (unsigned)(wid * STG_ROW + j0 * 2 + (lane >> 3) * 16);
    }
    unsigned pmbar = 0;
    if (wid == 0 && lane < 16)
        asm("mapa.shared::cluster.u32 %0, %1, %2;" : "=r"(pmbar) : "r"(mbar0), "r"(lane));

    int ph0 = 0, ph1 = 0;
    float cst = 0.f;

    for (int s = 0; s < TT; s++) {
        int p = s & 1;
        int t = dir ? (TT - 1 - s) : s;

        const __nv_bfloat16* xrow = xw + (size_t)(t * BB + bg * 16 + wid) * G4 + j0 + lane;
        float xq0 = __bfloat162float(xrow[0]);
        float xq1 = __bfloat162float(xrow[512]);
        float xq2 = __bfloat162float(xrow[1024]);
        float xq3 = __bfloat162float(xrow[1536]);

        if (s) {
            unsigned mb = mbar0 + p * 8;
            int phv = p ? ph1 : ph0;
            asm volatile(
                "{\n\t.reg .pred P;\n"
                "WL%=:\n\t"
                "mbarrier.try_wait.parity.acquire.cluster.shared::cta.b64 P, [%0], %1, 0x989680;\n\t"
                "@P bra WD%=;\n\t"
                "bra WL%=;\n"
                "WD%=:\n\t}"
                :: "r"(mb), "r"(phv) : "memory");
            if (p) ph1 ^= 1; else ph0 ^= 1;
        }

        unsigned stgp = stg0 + (unsigned)(p * STG_PAR);
        float acc[2][4];
#pragma unroll
        for (int i = 0; i < 2; i++)
#pragma unroll
            for (int j = 0; j < 4; j++) acc[i][j] = 0.f;

#pragma unroll
        for (int kk = 0; kk < 16; kk++) {
            int k0 = kbase + kk * 16;
            unsigned a[4];
            unsigned addr = stgp + (unsigned)((lane & 15) * STG_ROW + k0 * 2 + (lane >> 4) * 16);
            asm volatile("ldmatrix.sync.aligned.m8n8.x4.shared.b16 {%0,%1,%2,%3}, [%4];\n"
                         : "=r"(a[0]), "=r"(a[1]), "=r"(a[2]), "=r"(a[3]) : "r"(addr));
#pragma unroll
            for (int nt = 0; nt < 2; nt++) {
                asm volatile(
                    "mma.sync.aligned.m16n8k16.row.col.f32.bf16.bf16.f32 "
                    "{%0,%1,%2,%3}, {%4,%5,%6,%7}, {%8,%9}, {%0,%1,%2,%3};\n"
                    : "+f"(acc[nt][0]), "+f"(acc[nt][1]), "+f"(acc[nt][2]), "+f"(acc[nt][3])
                    : "r"(a[0]), "r"(a[1]), "r"(a[2]), "r"(a[3]),
                      "r"(bfr[kk][nt * 2]), "r"(bfr[kk][nt * 2 + 1]));
            }
        }

        {
            int r = lane >> 2;
            int cb = ngc + (lane & 3) * 2;
#pragma unroll
            for (int nt = 0; nt < 2; nt++) {
                *(float2*)(gw + r * GPAD + cb + nt * 8)       = make_float2(acc[nt][0], acc[nt][1]);
                *(float2*)(gw + (r + 8) * GPAD + cb + nt * 8) = make_float2(acc[nt][2], acc[nt][3]);
            }
        }
        __syncthreads();

        float h;
        {
            float gi = gatesA[wid * GPAD + lane]      + gatesB[wid * GPAD + lane]      + xq0;
            float gf = gatesA[wid * GPAD + 32 + lane] + gatesB[wid * GPAD + 32 + lane] + xq1;
            float gg = gatesA[wid * GPAD + 64 + lane] + gatesB[wid * GPAD + 64 + lane] + xq2;
            float go = gatesA[wid * GPAD + 96 + lane] + gatesB[wid * GPAD + 96 + lane] + xq3;
            float si = 0.5f * tanha(0.5f * gi) + 0.5f;
            float sf = 0.5f * tanha(0.5f * gf) + 0.5f;
            float so = 0.5f * tanha(0.5f * go) + 0.5f;
            cst = sf * cst + si * tanha(gg);
            h = so * tanha(cst);
        }
        __nv_bfloat16 hb16 = __float2bfloat16(h);
        g_hsb[(size_t)(t * BB + bg * 16 + wid) * (2 * HH) + dir * HH + j0 + lane] = hb16;

        if (s + 1 < TT) {
            unsigned hb = (unsigned)(*(unsigned short*)&hb16);
            unsigned o1 = __shfl_xor_sync(0xffffffffu, hb, 1);
            unsigned p32 = (lane & 1) ? ((hb << 16) | o1) : ((o1 << 16) | hb);
            unsigned o2 = __shfl_xor_sync(0xffffffffu, p32, 2);
            unsigned lo = (lane & 2) ? o2 : p32;
            unsigned hi = (lane & 2) ? p32 : o2;
            unsigned lo2 = __shfl_xor_sync(0xffffffffu, lo, 4);
            unsigned hi2 = __shfl_xor_sync(0xffffffffu, hi, 4);
            unsigned r0 = (lane & 4) ? lo2 : lo;
            unsigned r1 = (lane & 4) ? hi2 : hi;
            unsigned r2 = (lane & 4) ? lo : lo2;
            unsigned r3 = (lane & 4) ? hi : hi2;
            unsigned off = (unsigned)((p ^ 1) * STG_PAR);
#pragma unroll
            for (int i = 0; i < 2; i++)
                asm volatile("st.shared::cluster.v4.b32 [%0], {%1,%2,%3,%4};"
                             :: "r"(pst[i] + off), "r"(r0), "r"(r1), "r"(r2), "r"(r3) : "memory");
            __syncthreads();
            if (wid == 0 && lane < 16)
                asm volatile("mbarrier.arrive.release.cluster.shared::cluster.b64 _, [%0];"
                             :: "r"(pmbar + (unsigned)((p ^ 1) * 8)) : "memory");
        }
    }

    asm volatile("barrier.cluster.arrive.aligned;" ::: "memory");
    asm volatile("barrier.cluster.wait.aligned;" ::: "memory");
}

// ------------------------- tag projection: bf16 mma GEMM -------------------------
#define TBK 64
#define TB_STRIDE 40
#define TA_STRIDE 72
#define TA_BUF (128 * TA_STRIDE)
#define TSMEM ((1024 * TB_STRIDE + 2 * TA_BUF) * 2)

__global__ __launch_bounds__(256) void k_tag(const float* __restrict__ Wtag,
                                             const float* __restrict__ btag)
{
    extern __shared__ char tsm[];
    __nv_bfloat16* Bt = (__nv_bfloat16*)tsm;
    __nv_bfloat16* As = Bt + 1024 * TB_STRIDE;

    int tid = threadIdx.x;
    int wid = tid >> 5;
    int lane = tid & 31;
    int m0 = blockIdx.x * 128;

    for (int idx = tid; idx < 1024 * 32; idx += 256) {
        int k = idx >> 5, n = idx & 31;
        float v = (n < KK) ? Wtag[k * KK + n] : 0.f;
        Bt[k * TB_STRIDE + n] = __float2bfloat16(v);
    }

    auto loadA = [&](int buf, int k0) {
        __nv_bfloat16* Ab = As + buf * TA_BUF;
#pragma unroll
        for (int j = 0; j < 4; j++) {
            int c = tid + j * 256;
            int r = c >> 3, q = c & 7;
            unsigned dst = smaddr(Ab + r * TA_STRIDE + q * 8);
            const __nv_bfloat16* src = g_hsb + (size_t)(m0 + r) * 1024 + k0 + q * 8;
            asm volatile("cp.async.cg.shared.global [%0], [%1], 16;\n" :: "r"(dst), "l"(src));
        }
    };

    loadA(0, 0);
    asm volatile("cp.async.commit_group;\n");
    __syncthreads();

    float acc[4][4];
#pragma unroll
    for (int i = 0; i < 4; i++)
#pragma unroll
        for (int j = 0; j < 4; j++) acc[i][j] = 0.f;

    for (int kt = 0; kt < 1024 / TBK; kt++) {
        int buf = kt & 1;
        if (kt + 1 < 1024 / TBK) {
            loadA(buf ^ 1, (kt + 1) * TBK);
            asm volatile("cp.async.commit_group;\n");
            asm volatile("cp.async.wait_group 1;\n");
        } else {
            asm volatile("cp.async.wait_group 0;\n");
        }
        __syncthreads();
        __nv_bfloat16* Ab = As + buf * TA_BUF;
#pragma unroll
        for (int ks = 0; ks < 4; ks++) {
            int k0 = ks * 16;
            int kabs = kt * TBK + k0;
            unsigned a[4];
            unsigned addr = smaddr(Ab + (wid * 16 + (lane & 15)) * TA_STRIDE + k0 + 8 * (lane >> 4));
            asm volatile("ldmatrix.sync.aligned.m8n8.x4.shared.b16 {%0,%1,%2,%3}, [%4];\n"
                         : "=r"(a[0]), "=r"(a[1]), "=r"(a[2]), "=r"(a[3]) : "r"(addr));
            unsigned b[2][4];
#pragma unroll
            for (int nj = 0; nj < 2; nj++) {
                unsigned baddr = smaddr(Bt + (kabs + (lane & 15)) * TB_STRIDE + nj * 16 + 8 * (lane >> 4));
                asm volatile("ldmatrix.sync.aligned.m8n8.x4.trans.shared.b16 {%0,%1,%2,%3}, [%4];\n"
                             : "=r"(b[nj][0]), "=r"(b[nj][1]), "=r"(b[nj][2]), "=r"(b[nj][3])
                             : "r"(baddr));
            }
#pragma unroll
            for (int ni = 0; ni < 4; ni++) {
                unsigned b0 = b[ni >> 1][(ni & 1) * 2];
                unsigned b1 = b[ni >> 1][(ni & 1) * 2 + 1];
                asm volatile(
                    "mma.sync.aligned.m16n8k16.row.col.f32.bf16.bf16.f32 "
                    "{%0,%1,%2,%3}, {%4,%5,%6,%7}, {%8,%9}, {%0,%1,%2,%3};\n"
                    : "+f"(acc[ni][0]), "+f"(acc[ni][1]), "+f"(acc[ni][2]), "+f"(acc[ni][3])
                    : "r"(a[0]), "r"(a[1]), "r"(a[2]), "r"(a[3]), "r"(b0), "r"(b1));
            }
        }
        __syncthreads();
    }

#pragma unroll
    for (int ni = 0; ni < 4; ni++) {
        int col = ni * 8 + (lane & 3) * 2;
#pragma unroll
        for (int half = 0; half < 2; half++) {
            int m = m0 + wid * 16 + (lane >> 2) + half * 8;
            int b = m & 31, t = m >> 5;
            float* fo = g_feats + ((size_t)b * TT + t) * KK;
            if (col < KK)     fo[col]     = acc[ni][half * 2]     + btag[col];
            if (col + 1 < KK) fo[col + 1] = acc[ni][half * 2 + 1] + btag[col + 1];
        }
    }
}

// ------------------------- CRF NLL (one warp per sentence) -------------------------
__global__ void k_crf(const float* __restrict__ trans, const int* __restrict__ tags,
                      float* __restrict__ out)
{
    int b = blockIdx.x;
    int lane = threadIdx.x;
    float trow[KK];
    int lr = (lane < KK) ? lane : 0;
#pragma unroll
    for (int p = 0; p < KK; p++) trow[p] = trans[lr * KK + p];
    float alpha = (lane == TSTART) ? 0.f : NEGV;
    const float* fb = g_feats + (size_t)b * TT * KK;
    for (int t = 0; t < TT; t++) {
        float emit = (lane < KK) ? fb[t * KK + lane] : 0.f;
        float v[KK];
        float vmax = -1e30f;
#pragma unroll
        for (int p = 0; p < KK; p++) {
            v[p] = __shfl_sync(0xffffffffu, alpha, p) + trow[p];
            vmax = fmaxf(vmax, v[p]);
        }
        float ssum = 0.f;
#pragma unroll
        for (int p = 0; p < KK; p++) ssum += __expf(v[p] - vmax);
        float na = vmax + __logf(ssum) + emit;
        alpha = (lane < KK) ? na : NEGV;
    }
    float v = (lane < KK) ? (alpha + trans[TSTOP * KK + lane]) : -1e30f;
    float m = v;
#pragma unroll
    for (int off = 16; off; off >>= 1) m = fmaxf(m, __shfl_xor_sync(0xffffffffu, m, off));
    float e = (lane < KK) ? __expf(v - m) : 0.f;
#pragma unroll
    for (int off = 16; off; off >>= 1) e += __shfl_xor_sync(0xffffffffu, e, off);
    float logz = m + __logf(e);
    const int* tg = tags + b * TT;
    float gold = 0.f;
    for (int j = lane; j < TT + 1; j += 32) {
        int prev = (j == 0) ? TSTART : tg[j - 1];
        int nxt  = (j < TT) ? tg[j] : TSTOP;
        gold += trans[nxt * KK + prev];
        if (j < TT) gold += fb[j * KK + tg[j]];
    }
#pragma unroll
    for (int off = 16; off; off >>= 1) gold += __shfl_xor_sync(0xffffffffu, gold, off);
    if (lane == 0) out[b] = logz - gold;
}

// ------------------------- launcher -------------------------
extern "C" void kernel_launch(void* const* d_in, const int* in_sizes, int n_in,
                              void* d_out, int out_size)
{
    const int*   ids   = (const int*)  d_in[0];
    const int*   tags  = (const int*)  d_in[1];
    const float* embed = (const float*)d_in[2];
    const float* Wihf  = (const float*)d_in[3];
    const float* Whhf  = (const float*)d_in[4];
    const float* bf    = (const float*)d_in[5];
    const float* Wihb  = (const float*)d_in[6];
    const float* Whhb  = (const float*)d_in[7];
    const float* bb    = (const float*)d_in[8];
    const float* Wtag  = (const float*)d_in[9];
    const float* btag  = (const float*)d_in[10];
    const float* trans = (const float*)d_in[11];
    float* out = (float*)d_out;

    cudaFuncSetAttribute(k_gemm, cudaFuncAttributeMaxDynamicSharedMemorySize, GSMEM);
    cudaFuncSetAttribute(k_tag,  cudaFuncAttributeMaxDynamicSharedMemorySize, TSMEM);
    cudaFuncSetAttribute(k_lstm2, cudaFuncAttributeMaxDynamicSharedMemorySize, LSM_BYTES);
    cudaFuncSetAttribute(k_lstm2, cudaFuncAttributeNonPortableClusterSizeAllowed, 1);

    {
        size_t nx = (size_t)MTOT * (DIN / 4);
        k_castx<<<(unsigned)((nx + 255) / 256), 256>>>(embed, ids);
        size_t nwt = 2 * NW4 + 2 * NH4;
        k_castw<<<(unsigned)((nwt + 255) / 256), 256>>>(Wihf, Wihb, Whhf, Whhb);
    }
    k_gemm<<<dim3(16, MTOT / BM), 256, GSMEM>>>(bf, bb);
    k_lstm2<<<64, 512, LSM_BYTES>>>();
    k_tag<<<MTOT / 128, 256, TSMEM>>>(Wtag, btag);
    k_crf<<<BB, 32>>>(trans, tags, out);
}

// round 15
// speedup vs baseline: 1.5082x; 1.0312x over previous
#include <cuda_runtime.h>
#include <cuda_bf16.h>
#include <cuda_fp8.h>
#include <math.h>

#define BB 32
#define TT 512
#define DIN 1824
#define HH 512
#define G4 2048
#define KK 30
#define TSTART 28
#define TSTOP 29
#define NEGV (-10000.0f)
#define MTOT (TT*BB)            /* 16384 */

#define SX 16.0f
#define SW 64.0f
#define OSCALE (1.0f/1024.0f)

// ------------------------- device scratch -------------------------
__device__ __nv_bfloat16 g_xwb[2][(size_t)MTOT*G4];  // input proj, bf16
__device__ __nv_bfloat16 g_hsb[(size_t)MTOT*2*HH];   // [m][hf|hb] bf16, m=t*B+b
__device__ float g_feats[(size_t)BB*TT*KK];          // [b][t][k]
__device__ unsigned char g_x8[(size_t)MTOT*DIN];     // gathered embeddings, e4m3 (x16)
__device__ unsigned char g_wt8[2][(size_t)G4*DIN];   // W_ih^T f/b, e4m3 (x64), [n][k]
__device__ __nv_bfloat16 g_wb2[2][(size_t)HH*G4];    // W_hh f/b, bf16

__device__ __forceinline__ unsigned smaddr(const void* p)
{
    return (unsigned)__cvta_generic_to_shared(p);
}

__device__ __forceinline__ float tanha(float x)
{
    float r;
    asm("tanh.approx.f32 %0, %1;" : "=f"(r) : "f"(x));
    return r;
}

// ------------------------- cast kernels -------------------------
__global__ __launch_bounds__(256) void k_castx8(const float* __restrict__ embed,
                                                const int* __restrict__ ids)
{
    size_t idx = (size_t)blockIdx.x * 256 + threadIdx.x;   // over MTOT*228
    if (idx >= (size_t)MTOT * (DIN / 8)) return;
    int m = (int)(idx / (DIN / 8));
    int q = (int)(idx % (DIN / 8));
    int id = ids[(m & 31) * TT + (m >> 5)];
    const float* src = embed + (size_t)id * DIN + 8 * q;
    float4 v0 = *(const float4*)src;
    float4 v1 = *(const float4*)(src + 4);
    unsigned p0 = __nv_cvt_float2_to_fp8x2(make_float2(v0.x * SX, v0.y * SX), __NV_SATFINITE, __NV_E4M3);
    unsigned p1 = __nv_cvt_float2_to_fp8x2(make_float2(v0.z * SX, v0.w * SX), __NV_SATFINITE, __NV_E4M3);
    unsigned p2 = __nv_cvt_float2_to_fp8x2(make_float2(v1.x * SX, v1.y * SX), __NV_SATFINITE, __NV_E4M3);
    unsigned p3 = __nv_cvt_float2_to_fp8x2(make_float2(v1.z * SX, v1.w * SX), __NV_SATFINITE, __NV_E4M3);
    uint2 pk;
    pk.x = (p0 & 0xffffu) | (p1 << 16);
    pk.y = (p2 & 0xffffu) | (p3 << 16);
    *(uint2*)(g_x8 + (size_t)m * DIN + 8 * q) = pk;
}

// transpose + cast W_ih -> Wt[n][k] e4m3. Tile 32k x 128n per block; 912 tiles/dir.
__global__ __launch_bounds__(256) void k_castw8t(const float* __restrict__ Wf,
                                                 const float* __restrict__ Wb)
{
    __shared__ __align__(16) unsigned char St[128][48];
    int b = blockIdx.x;                 // 0..1823
    int dir = b / 912;
    int rem = b - dir * 912;
    int k0 = (rem >> 4) * 32;
    int n0 = (rem & 15) * 128;
    const float* W = dir ? Wb : Wf;
    int t = threadIdx.x;
    int k = t >> 3;
    int nq = (t & 7) * 16;
    const float* row = W + (size_t)(k0 + k) * G4 + n0 + nq;
#pragma unroll
    for (int j4 = 0; j4 < 4; j4++) {
        float4 v = *(const float4*)(row + j4 * 4);
        St[nq + j4 * 4 + 0][k] = __nv_cvt_float_to_fp8(v.x * SW, __NV_SATFINITE, __NV_E4M3);
        St[nq + j4 * 4 + 1][k] = __nv_cvt_float_to_fp8(v.y * SW, __NV_SATFINITE, __NV_E4M3);
        St[nq + j4 * 4 + 2][k] = __nv_cvt_float_to_fp8(v.z * SW, __NV_SATFINITE, __NV_E4M3);
        St[nq + j4 * 4 + 3][k] = __nv_cvt_float_to_fp8(v.w * SW, __NV_SATFINITE, __NV_E4M3);
    }
    __syncthreads();
    int n = t >> 1, half = t & 1;
    uint4 val = *(const uint4*)(&St[n][half * 16]);
    *(uint4*)(g_wt8[dir] + (size_t)(n0 + n) * DIN + k0 + half * 16) = val;
}

// W_hh bf16 cast
#define NH4 ((size_t)HH*G4/4)
__global__ __launch_bounds__(256) void k_castw2(const float* __restrict__ f2,
                                                const float* __restrict__ f3)
{
    size_t idx = (size_t)blockIdx.x * 256 + threadIdx.x;
    const float* src; __nv_bfloat16* dst;
    if (idx < NH4)          { src = f2; dst = g_wb2[0]; }
    else if (idx < 2 * NH4) { src = f3; dst = g_wb2[1]; idx -= NH4; }
    else return;
    float4 v = *(const float4*)(src + 4 * idx);
    __nv_bfloat162 lo = __floats2bfloat162_rn(v.x, v.y);
    __nv_bfloat162 hi = __floats2bfloat162_rn(v.z, v.w);
    uint2 pk; pk.x = *(unsigned*)&lo; pk.y = *(unsigned*)&hi;
    *(uint2*)(dst + 4 * idx) = pk;
}

// ------------- input GEMM: fp8 e4m3, BM128 x BN128 x BK32, m16n8k32 mma --------------
#define BM 128
#define BN 128
#define BK8 32
#define NKT8 57
#define AST 48                          /* 32 + 16 pad, 16B-aligned rows */
#define ABUF (BM * AST)                 /* 6144 B */
#define GSMEM8 (3 * 2 * ABUF)           /* 36864 B */

__global__ __launch_bounds__(256) void k_gemm8(const float* __restrict__ bf_,
                                               const float* __restrict__ bb_)
{
    extern __shared__ char gsm[];
    unsigned char* As = (unsigned char*)gsm;          // [3][128][48]
    unsigned char* Bs = As + 3 * ABUF;                // [3][128][48]

    int dir = blockIdx.x >> 4;
    int n0 = (blockIdx.x & 15) * BN;
    const float* bias = dir ? bb_ : bf_;
    const unsigned char* A = g_x8;
    const unsigned char* Bw = g_wt8[dir];
    __nv_bfloat16* out = g_xwb[dir];

    int tid = threadIdx.x;
    int wid = tid >> 5;
    int lane = tid & 31;
    int m0 = blockIdx.y * BM;
    int wm = (wid & 3) * 32;
    int wn = (wid >> 2) * 64;

    float acc[2][8][4];
#pragma unroll
    for (int i = 0; i < 2; i++)
#pragma unroll
        for (int j = 0; j < 8; j++)
#pragma unroll
            for (int r = 0; r < 4; r++) acc[i][j][r] = 0.f;

    auto loadAB = [&](int buf, int k0) {
        int r = tid >> 1, c = tid & 1;
        unsigned dstA = smaddr(As + buf * ABUF + r * AST + c * 16);
        const unsigned char* srcA = A + (size_t)(m0 + r) * DIN + k0 + c * 16;
        asm volatile("cp.async.cg.shared.global [%0], [%1], 16;\n" :: "r"(dstA), "l"(srcA));
        unsigned dstB = smaddr(Bs + buf * ABUF + r * AST + c * 16);
        const unsigned char* srcB = Bw + (size_t)(n0 + r) * DIN + k0 + c * 16;
        asm volatile("cp.async.cg.shared.global [%0], [%1], 16;\n" :: "r"(dstB), "l"(srcB));
    };

    loadAB(0, 0);
    asm volatile("cp.async.commit_group;\n");
    loadAB(1, BK8);
    asm volatile("cp.async.commit_group;\n");

    int buf = 0;
    for (int kt = 0; kt < NKT8; kt++) {
        asm volatile("cp.async.wait_group 1;\n");
        __syncthreads();
        if (kt + 2 < NKT8) {
            int nb = buf + 2; if (nb >= 3) nb -= 3;
            loadAB(nb, (kt + 2) * BK8);
        }
        asm volatile("cp.async.commit_group;\n");

        unsigned char* Ab = As + buf * ABUF;
        unsigned char* Bb = Bs + buf * ABUF;
        unsigned a[2][4];
#pragma unroll
        for (int mi = 0; mi < 2; mi++) {
            unsigned addr = smaddr(Ab + (wm + mi * 16 + (lane & 15)) * AST + (lane >> 4) * 16);
            asm volatile("ldmatrix.sync.aligned.m8n8.x4.shared.b16 {%0,%1,%2,%3}, [%4];\n"
                         : "=r"(a[mi][0]), "=r"(a[mi][1]), "=r"(a[mi][2]), "=r"(a[mi][3])
                         : "r"(addr));
        }
        unsigned bfrag[4][4];
#pragma unroll
        for (int nj = 0; nj < 4; nj++) {
            unsigned addr = smaddr(Bb + (wn + nj * 16 + (lane & 15)) * AST + (lane >> 4) * 16);
            asm volatile("ldmatrix.sync.aligned.m8n8.x4.shared.b16 {%0,%1,%2,%3}, [%4];\n"
                         : "=r"(bfrag[nj][0]), "=r"(bfrag[nj][1]), "=r"(bfrag[nj][2]), "=r"(bfrag[nj][3])
                         : "r"(addr));
        }
#pragma unroll
        for (int mi = 0; mi < 2; mi++)
#pragma unroll
            for (int nj = 0; nj < 4; nj++) {
                // n8 group 0 (rows nj*16+0..7): frags {r0, r2}
                asm volatile(
                    "mma.sync.aligned.m16n8k32.row.col.f32.e4m3.e4m3.f32 "
                    "{%0,%1,%2,%3}, {%4,%5,%6,%7}, {%8,%9}, {%0,%1,%2,%3};\n"
                    : "+f"(acc[mi][nj * 2][0]), "+f"(acc[mi][nj * 2][1]),
                      "+f"(acc[mi][nj * 2][2]), "+f"(acc[mi][nj * 2][3])
                    : "r"(a[mi][0]), "r"(a[mi][1]), "r"(a[mi][2]), "r"(a[mi][3]),
                      "r"(bfrag[nj][0]), "r"(bfrag[nj][2]));
                // n8 group 1 (rows nj*16+8..15): frags {r1, r3}
                asm volatile(
                    "mma.sync.aligned.m16n8k32.row.col.f32.e4m3.e4m3.f32 "
                    "{%0,%1,%2,%3}, {%4,%5,%6,%7}, {%8,%9}, {%0,%1,%2,%3};\n"
                    : "+f"(acc[mi][nj * 2 + 1][0]), "+f"(acc[mi][nj * 2 + 1][1]),
                      "+f"(acc[mi][nj * 2 + 1][2]), "+f"(acc[mi][nj * 2 + 1][3])
                    : "r"(a[mi][0]), "r"(a[mi][1]), "r"(a[mi][2]), "r"(a[mi][3]),
                      "r"(bfrag[nj][1]), "r"(bfrag[nj][3]));
            }
        __syncthreads();
        if (++buf == 3) buf = 0;
    }

#pragma unroll
    for (int mi = 0; mi < 2; mi++) {
#pragma unroll
        for (int ni = 0; ni < 8; ni++) {
            int col = n0 + wn + ni * 8 + (lane & 3) * 2;
            float bx = bias[col], by = bias[col + 1];
            int row0 = m0 + wm + mi * 16 + (lane >> 2);
            __nv_bfloat162 v0 = __floats2bfloat162_rn(acc[mi][ni][0] * OSCALE + bx,
                                                      acc[mi][ni][1] * OSCALE + by);
            __nv_bfloat162 v1 = __floats2bfloat162_rn(acc[mi][ni][2] * OSCALE + bx,
                                                      acc[mi][ni][3] * OSCALE + by);
            *(__nv_bfloat162*)(out + (size_t)row0 * G4 + col) = v0;
            *(__nv_bfloat162*)(out + (size_t)(row0 + 8) * G4 + col) = v1;
        }
    }
}

// ------------------------- LSTM: R9 exact (4 clusters x 16 CTAs, dual gates) ----------
#define WPAD 136
#define SPAD 520
#define GPAD 136
#define STG_ROW   (SPAD*2)
#define STG_PAR   (16*STG_ROW)
#define OFF_STG   (512*WPAD*2)
#define OFF_GATES (OFF_STG + 2*STG_PAR)
#define OFF_MBAR  (OFF_GATES + 2*16*GPAD*4)
#define LSM_BYTES (OFF_MBAR + 64)

__global__ __launch_bounds__(512, 1) __cluster_dims__(16, 1, 1)
void k_lstm2(void)
{
    extern __shared__ char smraw[];
    __nv_bfloat16* Ws = (__nv_bfloat16*)smraw;
    float* gatesA = (float*)(smraw + OFF_GATES);
    float* gatesB = gatesA + 16 * GPAD;

    int tid = threadIdx.x;
    int wid = tid >> 5;
    int lane = tid & 31;
    int cid = blockIdx.x >> 4;
    int rank = blockIdx.x & 15;
    int dir = cid >> 1;
    int bg  = cid & 1;
    int j0  = rank * 32;

    const __nv_bfloat16* Whh = g_wb2[dir];
    const __nv_bfloat16* xw = g_xwb[dir];

    unsigned sbase = smaddr(smraw);
    unsigned stg0  = sbase + OFF_STG;
    unsigned mbar0 = sbase + OFF_MBAR;

    if (tid == 0) {
        asm volatile("mbarrier.init.shared.b64 [%0], 16;" :: "r"(mbar0) : "memory");
        asm volatile("mbarrier.init.shared.b64 [%0], 16;" :: "r"(mbar0 + 8) : "memory");
    }
    for (int c = tid; c < STG_PAR / 8; c += 512)
        ((uint2*)(smraw + OFF_STG))[c] = make_uint2(0, 0);
    for (int c = tid; c < 512 * 16; c += 512) {
        int k = c >> 4, ch = c & 15;
        int q = ch >> 2, jb = (ch & 3) * 8;
        uint4 v = *(const uint4*)(Whh + (size_t)k * G4 + q * 512 + j0 + jb);
        *(uint4*)(Ws + k * WPAD + q * 32 + jb) = v;
    }
    __syncthreads();
    asm volatile("barrier.cluster.arrive.aligned;" ::: "memory");
    asm volatile("barrier.cluster.wait.aligned;" ::: "memory");

    int kh = wid & 1;
    int ng = wid >> 1;
    int kbase = kh * 256;
    int ngc = ng * 16;
    float* gw = kh ? gatesB : gatesA;

    unsigned bfr[16][4];
#pragma unroll
    for (int kk = 0; kk < 16; kk++) {
        int k0 = kbase + kk * 16;
        unsigned addr = smaddr(Ws + (k0 + (lane & 15)) * WPAD + ngc + 8 * (lane >> 4));
        asm volatile("ldmatrix.sync.aligned.m8n8.x4.trans.shared.b16 {%0,%1,%2,%3}, [%4];\n"
                     : "=r"(bfr[kk][0]), "=r"(bfr[kk][1]), "=r"(bfr[kk][2]), "=r"(bfr[kk][3])
                     : "r"(addr));
    }

    unsigned pst[2];
#pragma unroll
    for (int i = 0; i < 2; i++) {
        unsigned tgt = (lane & 7) + 8 * i;
        unsigned r;
        asm("mapa.shared::cluster.u32 %0, %1, %2;" : "=r"(r) : "r"(stg0), "r"(tgt));
        pst[i] = r + (unsigned)(wid * STG_ROW + j0 * 2 + (lane >> 3) * 16);
    }
    unsigned pmbar = 0;
    if (wid == 0 && lane < 16)
        asm("mapa.shared::cluster.u32 %0, %1, %2;" : "=r"(pmbar) : "r"(mbar0), "r"(lane));

    int ph0 = 0, ph1 = 0;
    float cst = 0.f;

    for (int s = 0; s < TT; s++) {
        int p = s & 1;
        int t = dir ? (TT - 1 - s) : s;

        const __nv_bfloat16* xrow = xw + (size_t)(t * BB + bg * 16 + wid) * G4 + j0 + lane;
        float xq0 = __bfloat162float(xrow[0]);
        float xq1 = __bfloat162float(xrow[512]);
        float xq2 = __bfloat162float(xrow[1024]);
        float xq3 = __bfloat162float(xrow[1536]);

        if (s) {
            unsigned mb = mbar0 + p * 8;
            int phv = p ? ph1 : ph0;
            asm volatile(
                "{\n\t.reg .pred P;\n"
                "WL%=:\n\t"
                "mbarrier.try_wait.parity.acquire.cluster.shared::cta.b64 P, [%0], %1, 0x989680;\n\t"
                "@P bra WD%=;\n\t"
                "bra WL%=;\n"
                "WD%=:\n\t}"
                :: "r"(mb), "r"(phv) : "memory");
            if (p) ph1 ^= 1; else ph0 ^= 1;
        }

        unsigned stgp = stg0 + (unsigned)(p * STG_PAR);
        float acc[2][4];
#pragma unroll
        for (int i = 0; i < 2; i++)
#pragma unroll
            for (int j = 0; j < 4; j++) acc[i][j] = 0.f;

#pragma unroll
        for (int kk = 0; kk < 16; kk++) {
            int k0 = kbase + kk * 16;
            unsigned a[4];
            unsigned addr = stgp + (unsigned)((lane & 15) * STG_ROW + k0 * 2 + (lane >> 4) * 16);
            asm volatile("ldmatrix.sync.aligned.m8n8.x4.shared.b16 {%0,%1,%2,%3}, [%4];\n"
                         : "=r"(a[0]), "=r"(a[1]), "=r"(a[2]), "=r"(a[3]) : "r"(addr));
#pragma unroll
            for (int nt = 0; nt < 2; nt++) {
                asm volatile(
                    "mma.sync.aligned.m16n8k16.row.col.f32.bf16.bf16.f32 "
                    "{%0,%1,%2,%3}, {%4,%5,%6,%7}, {%8,%9}, {%0,%1,%2,%3};\n"
                    : "+f"(acc[nt][0]), "+f"(acc[nt][1]), "+f"(acc[nt][2]), "+f"(acc[nt][3])
                    : "r"(a[0]), "r"(a[1]), "r"(a[2]), "r"(a[3]),
                      "r"(bfr[kk][nt * 2]), "r"(bfr[kk][nt * 2 + 1]));
            }
        }

        {
            int r = lane >> 2;
            int cb = ngc + (lane & 3) * 2;
#pragma unroll
            for (int nt = 0; nt < 2; nt++) {
                *(float2*)(gw + r * GPAD + cb + nt * 8)       = make_float2(acc[nt][0], acc[nt][1]);
                *(float2*)(gw + (r + 8) * GPAD + cb + nt * 8) = make_float2(acc[nt][2], acc[nt][3]);
            }
        }
        __syncthreads();

        float h;
        {
            float gi = gatesA[wid * GPAD + lane]      + gatesB[wid * GPAD + lane]      + xq0;
            float gf = gatesA[wid * GPAD + 32 + lane] + gatesB[wid * GPAD + 32 + lane] + xq1;
            float gg = gatesA[wid * GPAD + 64 + lane] + gatesB[wid * GPAD + 64 + lane] + xq2;
            float go = gatesA[wid * GPAD + 96 + lane] + gatesB[wid * GPAD + 96 + lane] + xq3;
            float si = 0.5f * tanha(0.5f * gi) + 0.5f;
            float sf = 0.5f * tanha(0.5f * gf) + 0.5f;
            float so = 0.5f * tanha(0.5f * go) + 0.5f;
            cst = sf * cst + si * tanha(gg);
            h = so * tanha(cst);
        }
        __nv_bfloat16 hb16 = __float2bfloat16(h);
        g_hsb[(size_t)(t * BB + bg * 16 + wid) * (2 * HH) + dir * HH + j0 + lane] = hb16;

        if (s + 1 < TT) {
            unsigned hb = (unsigned)(*(unsigned short*)&hb16);
            unsigned o1 = __shfl_xor_sync(0xffffffffu, hb, 1);
            unsigned p32 = (lane & 1) ? ((hb << 16) | o1) : ((o1 << 16) | hb);
            unsigned o2 = __shfl_xor_sync(0xffffffffu, p32, 2);
            unsigned lo = (lane & 2) ? o2 : p32;
            unsigned hi = (lane & 2) ? p32 : o2;
            unsigned lo2 = __shfl_xor_sync(0xffffffffu, lo, 4);
            unsigned hi2 = __shfl_xor_sync(0xffffffffu, hi, 4);
            unsigned r0 = (lane & 4) ? lo2 : lo;
            unsigned r1 = (lane & 4) ? hi2 : hi;
            unsigned r2 = (lane & 4) ? lo : lo2;
            unsigned r3 = (lane & 4) ? hi : hi2;
            unsigned off = (unsigned)((p ^ 1) * STG_PAR);
#pragma unroll
            for (int i = 0; i < 2; i++)
                asm volatile("st.shared::cluster.v4.b32 [%0], {%1,%2,%3,%4};"
                             :: "r"(pst[i] + off), "r"(r0), "r"(r1), "r"(r2), "r"(r3) : "memory");
            __syncthreads();
            if (wid == 0 && lane < 16)
                asm volatile("mbarrier.arrive.release.cluster.shared::cluster.b64 _, [%0];"
                             :: "r"(pmbar + (unsigned)((p ^ 1) * 8)) : "memory");
        }
    }

    asm volatile("barrier.cluster.arrive.aligned;" ::: "memory");
    asm volatile("barrier.cluster.wait.aligned;" ::: "memory");
}

// ------------------------- tag projection: bf16 mma GEMM -------------------------
#define TBK 64
#define TB_STRIDE 40
#define TA_STRIDE 72
#define TA_BUF (128 * TA_STRIDE)
#define TSMEM ((1024 * TB_STRIDE + 2 * TA_BUF) * 2)

__global__ __launch_bounds__(256) void k_tag(const float* __restrict__ Wtag,
                                             const float* __restrict__ btag)
{
    extern __shared__ char tsm[];
    __nv_bfloat16* Bt = (__nv_bfloat16*)tsm;
    __nv_bfloat16* As = Bt + 1024 * TB_STRIDE;

    int tid = threadIdx.x;
    int wid = tid >> 5;
    int lane = tid & 31;
    int m0 = blockIdx.x * 128;

    for (int idx = tid; idx < 1024 * 32; idx += 256) {
        int k = idx >> 5, n = idx & 31;
        float v = (n < KK) ? Wtag[k * KK + n] : 0.f;
        Bt[k * TB_STRIDE + n] = __float2bfloat16(v);
    }

    auto loadA = [&](int buf, int k0) {
        __nv_bfloat16* Ab = As + buf * TA_BUF;
#pragma unroll
        for (int j = 0; j < 4; j++) {
            int c = tid + j * 256;
            int r = c >> 3, q = c & 7;
            unsigned dst = smaddr(Ab + r * TA_STRIDE + q * 8);
            const __nv_bfloat16* src = g_hsb + (size_t)(m0 + r) * 1024 + k0 + q * 8;
            asm volatile("cp.async.cg.shared.global [%0], [%1], 16;\n" :: "r"(dst), "l"(src));
        }
    };

    loadA(0, 0);
    asm volatile("cp.async.commit_group;\n");
    __syncthreads();

    float acc[4][4];
#pragma unroll
    for (int i = 0; i < 4; i++)
#pragma unroll
        for (int j = 0; j < 4; j++) acc[i][j] = 0.f;

    for (int kt = 0; kt < 1024 / TBK; kt++) {
        int buf = kt & 1;
        if (kt + 1 < 1024 / TBK) {
            loadA(buf ^ 1, (kt + 1) * TBK);
            asm volatile("cp.async.commit_group;\n");
            asm volatile("cp.async.wait_group 1;\n");
        } else {
            asm volatile("cp.async.wait_group 0;\n");
        }
        __syncthreads();
        __nv_bfloat16* Ab = As + buf * TA_BUF;
#pragma unroll
        for (int ks = 0; ks < 4; ks++) {
            int k0 = ks * 16;
            int kabs = kt * TBK + k0;
            unsigned a[4];
            unsigned addr = smaddr(Ab + (wid * 16 + (lane & 15)) * TA_STRIDE + k0 + 8 * (lane >> 4));
            asm volatile("ldmatrix.sync.aligned.m8n8.x4.shared.b16 {%0,%1,%2,%3}, [%4];\n"
                         : "=r"(a[0]), "=r"(a[1]), "=r"(a[2]), "=r"(a[3]) : "r"(addr));
            unsigned b[2][4];
#pragma unroll
            for (int nj = 0; nj < 2; nj++) {
                unsigned baddr = smaddr(Bt + (kabs + (lane & 15)) * TB_STRIDE + nj * 16 + 8 * (lane >> 4));
                asm volatile("ldmatrix.sync.aligned.m8n8.x4.trans.shared.b16 {%0,%1,%2,%3}, [%4];\n"
                             : "=r"(b[nj][0]), "=r"(b[nj][1]), "=r"(b[nj][2]), "=r"(b[nj][3])
                             : "r"(baddr));
            }
#pragma unroll
            for (int ni = 0; ni < 4; ni++) {
                unsigned b0 = b[ni >> 1][(ni & 1) * 2];
                unsigned b1 = b[ni >> 1][(ni & 1) * 2 + 1];
                asm volatile(
                    "mma.sync.aligned.m16n8k16.row.col.f32.bf16.bf16.f32 "
                    "{%0,%1,%2,%3}, {%4,%5,%6,%7}, {%8,%9}, {%0,%1,%2,%3};\n"
                    : "+f"(acc[ni][0]), "+f"(acc[ni][1]), "+f"(acc[ni][2]), "+f"(acc[ni][3])
                    : "r"(a[0]), "r"(a[1]), "r"(a[2]), "r"(a[3]), "r"(b0), "r"(b1));
            }
        }
        __syncthreads();
    }

#pragma unroll
    for (int ni = 0; ni < 4; ni++) {
        int col = ni * 8 + (lane & 3) * 2;
#pragma unroll
        for (int half = 0; half < 2; half++) {
            int m = m0 + wid * 16 + (lane >> 2) + half * 8;
            int b = m & 31, t = m >> 5;
            float* fo = g_feats + ((size_t)b * TT + t) * KK;
            if (col < KK)     fo[col]     = acc[ni][half * 2]     + btag[col];
            if (col + 1 < KK) fo[col + 1] = acc[ni][half * 2 + 1] + btag[col + 1];
        }
    }
}

// ------------------------- CRF NLL (one warp per sentence) -------------------------
__global__ void k_crf(const float* __restrict__ trans, const int* __restrict__ tags,
                      float* __restrict__ out)
{
    int b = blockIdx.x;
    int lane = threadIdx.x;
    float trow[KK];
    int lr = (lane < KK) ? lane : 0;
#pragma unroll
    for (int p = 0; p < KK; p++) trow[p] = trans[lr * KK + p];
    float alpha = (lane == TSTART) ? 0.f : NEGV;
    const float* fb = g_feats + (size_t)b * TT * KK;
    for (int t = 0; t < TT; t++) {
        float emit = (lane < KK) ? fb[t * KK + lane] : 0.f;
        float v[KK];
        float vmax = -1e30f;
#pragma unroll
        for (int p = 0; p < KK; p++) {
            v[p] = __shfl_sync(0xffffffffu, alpha, p) + trow[p];
            vmax = fmaxf(vmax, v[p]);
        }
        float ssum = 0.f;
#pragma unroll
        for (int p = 0; p < KK; p++) ssum += __expf(v[p] - vmax);
        float na = vmax + __logf(ssum) + emit;
        alpha = (lane < KK) ? na : NEGV;
    }
    float v = (lane < KK) ? (alpha + trans[TSTOP * KK + lane]) : -1e30f;
    float m = v;
#pragma unroll
    for (int off = 16; off; off >>= 1) m = fmaxf(m, __shfl_xor_sync(0xffffffffu, m, off));
    float e = (lane < KK) ? __expf(v - m) : 0.f;
#pragma unroll
    for (int off = 16; off; off >>= 1) e += __shfl_xor_sync(0xffffffffu, e, off);
    float logz = m + __logf(e);
    const int* tg = tags + b * TT;
    float gold = 0.f;
    for (int j = lane; j < TT + 1; j += 32) {
        int prev = (j == 0) ? TSTART : tg[j - 1];
        int nxt  = (j < TT) ? tg[j] : TSTOP;
        gold += trans[nxt * KK + prev];
        if (j < TT) gold += fb[j * KK + tg[j]];
    }
#pragma unroll
    for (int off = 16; off; off >>= 1) gold += __shfl_xor_sync(0xffffffffu, gold, off);
    if (lane == 0) out[b] = logz - gold;
}

// ------------------------- launcher -------------------------
extern "C" void kernel_launch(void* const* d_in, const int* in_sizes, int n_in,
                              void* d_out, int out_size)
{
    const int*   ids   = (const int*)  d_in[0];
    const int*   tags  = (const int*)  d_in[1];
    const float* embed = (const float*)d_in[2];
    const float* Wihf  = (const float*)d_in[3];
    const float* Whhf  = (const float*)d_in[4];
    const float* bf    = (const float*)d_in[5];
    const float* Wihb  = (const float*)d_in[6];
    const float* Whhb  = (const float*)d_in[7];
    const float* bb    = (const float*)d_in[8];
    const float* Wtag  = (const float*)d_in[9];
    const float* btag  = (const float*)d_in[10];
    const float* trans = (const float*)d_in[11];
    float* out = (float*)d_out;

    cudaFuncSetAttribute(k_gemm8, cudaFuncAttributeMaxDynamicSharedMemorySize, GSMEM8);
    cudaFuncSetAttribute(k_tag,   cudaFuncAttributeMaxDynamicSharedMemorySize, TSMEM);
    cudaFuncSetAttribute(k_lstm2, cudaFuncAttributeMaxDynamicSharedMemorySize, LSM_BYTES);
    cudaFuncSetAttribute(k_lstm2, cudaFuncAttributeNonPortableClusterSizeAllowed, 1);

    {
        size_t nx = (size_t)MTOT * (DIN / 8);
        k_castx8<<<(unsigned)((nx + 255) / 256), 256>>>(embed, ids);
        k_castw8t<<<1824, 256>>>(Wihf, Wihb);
        size_t nh = 2 * NH4;
        k_castw2<<<(unsigned)((nh + 255) / 256), 256>>>(Whhf, Whhb);
    }
    k_gemm8<<<dim3(32, MTOT / BM), 256, GSMEM8>>>(bf, bb);
    k_lstm2<<<64, 512, LSM_BYTES>>>();
    k_tag<<<MTOT / 128, 256, TSMEM>>>(Wtag, btag);
    k_crf<<<BB, 32>>>(trans, tags, out);
}